// round 2
// baseline (speedup 1.0000x reference)
#include <cuda_runtime.h>
#include <cuda_bf16.h>
#include <cstdint>

#define Bb   2
#define Nn   16384
#define Tt   2048
#define Dd   128
#define Ss   384
#define NWw  512
#define WQq  32
#define Hh   128
#define Ll   3
#define NHh  4
#define DHh  32
#define NTOKk 33
#define BN   (Bb*Nn)          // 32768
#define BKV  (Bb*NWw*Hh)      // 131072
#define PL   196608           // packed weights per layer (floats)

// ---------------- scratch (device globals; allocation-free) ----------------
__device__ float g_q   [BN*Dd];
__device__ float g_cn  [BN*Dd];
__device__ float g_h   [BN*Dd];
__device__ float g_t1  [BN*256];
__device__ float g_t2  [BN*256];
__device__ float g_t3  [BN*Dd];
__device__ float g_kv  [(size_t)BKV*256];   // also reused for FFN (BN*512 fits)
__device__ float g_aw  [Bb*Tt*Dd];
__device__ float g_sf  [Bb*Tt*Dd];
__device__ float g_wp  [Ll*PL];
__device__ int   g_tok [BN];
__device__ int   g_rm  [BKV];

__device__ __forceinline__ float sigf(float x){ return 1.f/(1.f + __expf(-x)); }

// ---------------- generic tiled SGEMM: C[M,N] = A[M,K] @ B[K,N] -------------
// M,N multiples of 128, K multiple of 32. Optional rowmap gathers A rows.
__global__ __launch_bounds__(256) void sgemm(
    const float* __restrict__ A, const float* __restrict__ Bm,
    float* __restrict__ C, int M, int N, int K, const int* __restrict__ rowmap)
{
    __shared__ float As[32*128];
    __shared__ float Bs[32*128];
    const int tid = threadIdx.x;
    const int m0 = blockIdx.y * 128;
    const int n0 = blockIdx.x * 128;
    const int tx = tid & 15, ty = tid >> 4;

    int arows[4];
#pragma unroll
    for (int i = 0; i < 4; i++) {
        int s = tid + i*256;
        int r = m0 + (s >> 3);
        arows[i] = rowmap ? rowmap[r] : r;
    }

    float acc[8][8];
#pragma unroll
    for (int i = 0; i < 8; i++)
#pragma unroll
        for (int j = 0; j < 8; j++) acc[i][j] = 0.f;

    for (int kt = 0; kt < K; kt += 32) {
#pragma unroll
        for (int i = 0; i < 4; i++) {
            int s = tid + i*256;
            int row = s >> 3;
            int k4  = (s & 7) << 2;
            float4 v = *(const float4*)(A + (size_t)arows[i]*K + kt + k4);
            As[(k4+0)*128 + row] = v.x;
            As[(k4+1)*128 + row] = v.y;
            As[(k4+2)*128 + row] = v.z;
            As[(k4+3)*128 + row] = v.w;
        }
#pragma unroll
        for (int i = 0; i < 4; i++) {
            int s = tid + i*256;
            int k  = s >> 5;
            int n4 = (s & 31) << 2;
            *(float4*)(Bs + k*128 + n4) =
                *(const float4*)(Bm + (size_t)(kt + k)*N + n0 + n4);
        }
        __syncthreads();
#pragma unroll
        for (int kk = 0; kk < 32; kk++) {
            float a[8], b[8];
            *(float4*)(a  ) = *(float4*)(As + kk*128 + ty*8);
            *(float4*)(a+4) = *(float4*)(As + kk*128 + ty*8 + 4);
            *(float4*)(b  ) = *(float4*)(Bs + kk*128 + tx*8);
            *(float4*)(b+4) = *(float4*)(Bs + kk*128 + tx*8 + 4);
#pragma unroll
            for (int i = 0; i < 8; i++)
#pragma unroll
                for (int j = 0; j < 8; j++) acc[i][j] += a[i]*b[j];
        }
        __syncthreads();
    }
#pragma unroll
    for (int i = 0; i < 8; i++) {
        size_t r = (size_t)(m0 + ty*8 + i);
        *(float4*)(C + r*N + n0 + tx*8    ) = *(float4*)(acc[i]);
        *(float4*)(C + r*N + n0 + tx*8 + 4) = *(float4*)(acc[i]+4);
    }
}

// ---------------- attention: one block per (head, window, batch) ------------
__global__ __launch_bounds__(128) void attn_kernel(
    const float* __restrict__ kv,     // (B*NW*H, 256): [K | V]
    const float* __restrict__ qg,     // (B*N, 256):   [Q | G]
    const float* __restrict__ bias,   // (B,NW,NH,WQ,H)
    const float* __restrict__ mask,   // (B,N)
    const int*   __restrict__ kidx,   // (NW*H)
    float* __restrict__ obuf)         // (B*N, 128)
{
    __shared__ float qs[32*33];
    __shared__ float ks[128*33];      // K, later reused for V
    __shared__ float sc[32*129];
    __shared__ float mv[128];
    const int t  = threadIdx.x;
    const int hd = blockIdx.x, w = blockIdx.y, b = blockIdx.z;
    const size_t kvbase = ((size_t)(b*NWw + w) * Hh) * 256 + hd*32;
    const size_t qbase  = ((size_t)(b*Nn + w*WQq)) * 256 + hd*32;

#pragma unroll
    for (int i = 0; i < 8; i++) {
        int s = t + i*128;
        int qq = s >> 5, d = s & 31;
        qs[qq*33 + d] = qg[qbase + (size_t)qq*256 + d];
    }
#pragma unroll
    for (int i = 0; i < 32; i++) {
        int s = t + i*128;
        int kk = s >> 5, d = s & 31;
        ks[kk*33 + d] = kv[kvbase + (size_t)kk*256 + d];
    }
    {
        int ki = kidx[w*Hh + t];
        mv[t] = (1.0f - mask[b*Nn + ki]) * -1e9f;
    }
    __syncthreads();

    // scores (thread t == key index)
    const float* bptr = bias + ((((size_t)b*NWw + w)*NHh + hd)*WQq)*Hh + t;
    const float mvt = mv[t];
#pragma unroll 4
    for (int qq = 0; qq < 32; qq++) {
        float a = 0.f;
#pragma unroll
        for (int d = 0; d < 32; d++) a += qs[qq*33 + d]*ks[t*33 + d];
        sc[qq*129 + t] = a*0.17677669529663689f + bptr[(size_t)qq*Hh] + mvt;
    }
    __syncthreads();

    // load V into ks while doing softmax on sc
#pragma unroll
    for (int i = 0; i < 32; i++) {
        int s = t + i*128;
        int kk = s >> 5, d = s & 31;
        ks[kk*33 + d] = kv[kvbase + (size_t)kk*256 + 128 + d];
    }
    {
        int qq = t >> 2, seg = t & 3;
        float* row = sc + qq*129 + seg*32;
        float mx = -1e30f;
#pragma unroll
        for (int j = 0; j < 32; j++) mx = fmaxf(mx, row[j]);
        mx = fmaxf(mx, __shfl_xor_sync(0xffffffffu, mx, 1));
        mx = fmaxf(mx, __shfl_xor_sync(0xffffffffu, mx, 2));
        float sum = 0.f;
#pragma unroll
        for (int j = 0; j < 32; j++) { float e = __expf(row[j]-mx); row[j] = e; sum += e; }
        sum += __shfl_xor_sync(0xffffffffu, sum, 1);
        sum += __shfl_xor_sync(0xffffffffu, sum, 2);
        float inv = 1.f/sum;
#pragma unroll
        for (int j = 0; j < 32; j++) row[j] *= inv;
    }
    __syncthreads();

    // O = attn @ V, gate with sigmoid(G), write
    {
        int qq = t >> 2, ds = (t & 3) * 8;
        float acc[8];
#pragma unroll
        for (int j = 0; j < 8; j++) acc[j] = 0.f;
#pragma unroll 8
        for (int k = 0; k < 128; k++) {
            float s = sc[qq*129 + k];
#pragma unroll
            for (int j = 0; j < 8; j++) acc[j] += s*ks[k*33 + ds + j];
        }
        size_t nrow = (size_t)(b*Nn + w*WQq + qq);
#pragma unroll
        for (int j = 0; j < 8; j++) {
            float g = qg[nrow*256 + 128 + hd*32 + ds + j];
            obuf[nrow*128 + hd*32 + ds + j] = acc[j] * sigf(g);
        }
    }
}

// ---------------- elementwise / small kernels ----------------
__global__ void ln_rows(const float* __restrict__ x, float* __restrict__ y) {
    int warp = threadIdx.x >> 5, lane = threadIdx.x & 31;
    size_t row = (size_t)blockIdx.x*8 + warp;
    float4 v = *(const float4*)(x + row*128 + lane*4);
    float s  = v.x+v.y+v.z+v.w;
    float ss = v.x*v.x+v.y*v.y+v.z*v.z+v.w*v.w;
#pragma unroll
    for (int o = 16; o; o >>= 1) { s += __shfl_xor_sync(~0u, s, o); ss += __shfl_xor_sync(~0u, ss, o); }
    float m = s*(1.f/128.f);
    float rstd = rsqrtf(ss*(1.f/128.f) - m*m + 1e-5f);
    float4 r;
    r.x = (v.x-m)*rstd; r.y = (v.y-m)*rstd; r.z = (v.z-m)*rstd; r.w = (v.w-m)*rstd;
    *(float4*)(y + row*128 + lane*4) = r;
}

// h = ln(q) * sigmoid(X[:, :128]) + X[:, 128:]
__global__ void ew_hcur(const float* __restrict__ q, const float* __restrict__ X,
                        float* __restrict__ h) {
    int warp = threadIdx.x >> 5, lane = threadIdx.x & 31;
    size_t row = (size_t)blockIdx.x*8 + warp;
    float4 v = *(const float4*)(q + row*128 + lane*4);
    float s  = v.x+v.y+v.z+v.w;
    float ss = v.x*v.x+v.y*v.y+v.z*v.z+v.w*v.w;
#pragma unroll
    for (int o = 16; o; o >>= 1) { s += __shfl_xor_sync(~0u, s, o); ss += __shfl_xor_sync(~0u, ss, o); }
    float m = s*(1.f/128.f);
    float rstd = rsqrtf(ss*(1.f/128.f) - m*m + 1e-5f);
    float4 g = *(const float4*)(X + row*256 + lane*4);
    float4 bb = *(const float4*)(X + row*256 + 128 + lane*4);
    float4 r;
    r.x = (v.x-m)*rstd*sigf(g.x) + bb.x;
    r.y = (v.y-m)*rstd*sigf(g.y) + bb.y;
    r.z = (v.z-m)*rstd*sigf(g.z) + bb.z;
    r.w = (v.w-m)*rstd*sigf(g.w) + bb.w;
    *(float4*)(h + row*128 + lane*4) = r;
}

// q += sigmoid(gate) * x   (elementwise over BN*128)
__global__ void ew_resid(float* __restrict__ q, const float* __restrict__ gate,
                         const float* __restrict__ x) {
    size_t i4 = (size_t)blockIdx.x*blockDim.x + threadIdx.x;   // BN*32 total
    float4 qq = *(float4*)(q + i4*4);
    float4 g  = *(const float4*)(gate + i4*4);
    float4 xx = *(const float4*)(x + i4*4);
    qq.x += sigf(g.x)*xx.x; qq.y += sigf(g.y)*xx.y;
    qq.z += sigf(g.z)*xx.z; qq.w += sigf(g.w)*xx.w;
    *(float4*)(q + i4*4) = qq;
}

// out[row,256] = silu(T[row, :256]) * T[row, 256:512]
__global__ void ew_glu(const float* __restrict__ T, float* __restrict__ out) {
    size_t i4 = (size_t)blockIdx.x*blockDim.x + threadIdx.x;   // BN*64 total
    size_t row = i4 >> 6;
    int c4 = (int)(i4 & 63) << 2;
    float4 a = *(const float4*)(T + row*512 + c4);
    float4 bb = *(const float4*)(T + row*512 + 256 + c4);
    float4 r;
    r.x = a.x*sigf(a.x)*bb.x; r.y = a.y*sigf(a.y)*bb.y;
    r.z = a.z*sigf(a.z)*bb.z; r.w = a.w*sigf(a.w)*bb.w;
    *(float4*)(out + row*256 + c4) = r;
}

__global__ void pack2(const float* __restrict__ s1, const float* __restrict__ s2,
                      float* __restrict__ dst, int K, int N1, int N2) {
    int tot = K*(N1+N2);
    for (int i = blockIdx.x*blockDim.x + threadIdx.x; i < tot; i += gridDim.x*blockDim.x) {
        int n = i % (N1+N2), k = i / (N1+N2);
        dst[i] = (n < N1) ? s1[k*N1 + n] : s2[k*N2 + n - N1];
    }
}

__global__ void rowmap_kernel(const int* __restrict__ kidx, int* __restrict__ rm) {
    int i = blockIdx.x*256 + threadIdx.x;         // BKV
    int b = i / (NWw*Hh);
    int r = i % (NWw*Hh);
    rm[i] = b*Nn + kidx[r];
}

__global__ void argmax_tok(const float* __restrict__ a2t, int* __restrict__ tok) {
    int warp = threadIdx.x >> 5, lane = threadIdx.x & 31;
    size_t row = (size_t)blockIdx.x*8 + warp;
    const float* p = a2t + row*Tt;
    float bv = -1e30f; int bi = 0;
    for (int j = lane; j < Tt; j += 32) { float v = p[j]; if (v > bv) { bv = v; bi = j; } }
#pragma unroll
    for (int o = 16; o; o >>= 1) {
        float ov = __shfl_xor_sync(~0u, bv, o);
        int   oi = __shfl_xor_sync(~0u, bi, o);
        if (ov > bv || (ov == bv && oi < bi)) { bv = ov; bi = oi; }
    }
    if (lane == 0) tok[row] = bi;
}

__global__ void addaw_kernel(const float* __restrict__ qin, const float* __restrict__ aw,
                             const int* __restrict__ tok, float* __restrict__ q) {
    size_t i4 = (size_t)blockIdx.x*256 + threadIdx.x;   // BN*32
    int row = (int)(i4 >> 5);
    int d4  = (int)(i4 & 31) << 2;
    int b = row >> 14;
    int t = tok[row];
    float4 v = *(const float4*)(qin + ((size_t)row << 7) + d4);
    float4 w = *(const float4*)(aw + (((size_t)b*Tt + t) << 7) + d4);
    v.x += w.x; v.y += w.y; v.z += w.z; v.w += w.w;
    *(float4*)(q + ((size_t)row << 7) + d4) = v;
}

__global__ void sfeat_kernel(const float* __restrict__ q, const float* __restrict__ mask,
                             const int* __restrict__ tok, float* __restrict__ sf) {
    size_t e = (size_t)blockIdx.x*256 + threadIdx.x;    // BN*128
    int row = (int)(e >> 7);
    int d = (int)(e & 127);
    int b = row >> 14;
    int t = tok[row];
    atomicAdd(&sf[(((size_t)b*Tt + t) << 7) + d], q[e]*mask[row]);
}

__global__ __launch_bounds__(128) void restype_kernel(
    const float* __restrict__ sf, const float* __restrict__ Wres,
    const float* __restrict__ bres, float* __restrict__ out) {
    __shared__ float sr[128];
    int t = threadIdx.x;
    size_t row = blockIdx.x;
    sr[t] = sf[row*128 + t];
    __syncthreads();
    if (t < NTOKk) {
        float acc = bres[t];
#pragma unroll 16
        for (int d = 0; d < 128; d++) acc += sr[d]*Wres[d*NTOKk + t];
        out[row*NTOKk + t] = acc;
    }
}

__global__ __launch_bounds__(128) void rupdate_kernel(
    const float* __restrict__ q, const float* __restrict__ g,
    const float* __restrict__ bb, const float* __restrict__ Wpos,
    float* __restrict__ out) {
    __shared__ float r1[128], r2[128];
    __shared__ float ms, rs;
    int d = threadIdx.x;
    size_t row = blockIdx.x;
    float x = q[row*128 + d];
    r1[d] = x; r2[d] = x*x;
    __syncthreads();
    for (int o = 64; o; o >>= 1) { if (d < o) { r1[d] += r1[d+o]; r2[d] += r2[d+o]; } __syncthreads(); }
    if (d == 0) {
        float m = r1[0]*(1.f/128.f);
        float v = r2[0]*(1.f/128.f) - m*m;
        ms = m; rs = rsqrtf(v + 1e-5f);
    }
    __syncthreads();
    float y = (x - ms)*rs*g[d] + bb[d];
    float p0 = y*Wpos[d*3], p1 = y*Wpos[d*3+1], p2 = y*Wpos[d*3+2];
    r1[d] = p0; r2[d] = p1;
    __syncthreads();
    for (int o = 64; o; o >>= 1) { if (d < o) { r1[d] += r1[d+o]; r2[d] += r2[d+o]; } __syncthreads(); }
    if (d == 0) { out[row*3] = r1[0]; out[row*3+1] = r2[0]; }
    __syncthreads();
    r1[d] = p2;
    __syncthreads();
    for (int o = 64; o; o >>= 1) { if (d < o) { r1[d] += r1[d+o]; } __syncthreads(); }
    if (d == 0) out[row*3+2] = r1[0];
}

// ---------------- host launcher ----------------
extern "C" void kernel_launch(void* const* d_in, const int* in_sizes, int n_in,
                              void* d_out, int out_size) {
    (void)in_sizes; (void)n_in; (void)out_size;
    const float* a    = (const float*)d_in[0];
    const float* qin  = (const float*)d_in[1];
    const float* c    = (const float*)d_in[2];
    const float* bias = (const float*)d_in[3];
    const float* a2t  = (const float*)d_in[4];
    const float* mask = (const float*)d_in[5];
    const int*   kidx = (const int*)  d_in[6];
    const float* a2q  = (const float*)d_in[7];
    const float* Wq   = (const float*)d_in[8];
    const float* Wk   = (const float*)d_in[9];
    const float* Wv   = (const float*)d_in[10];
    const float* Wg   = (const float*)d_in[11];
    const float* Wo   = (const float*)d_in[12];
    const float* Wcs  = (const float*)d_in[13];
    const float* Wcb  = (const float*)d_in[14];
    const float* Wog  = (const float*)d_in[15];
    const float* Wcs2 = (const float*)d_in[16];
    const float* Wcb2 = (const float*)d_in[17];
    const float* Wog2 = (const float*)d_in[18];
    const float* W1   = (const float*)d_in[19];
    const float* W2   = (const float*)d_in[20];
    const float* W3   = (const float*)d_in[21];
    const float* ln_g = (const float*)d_in[22];
    const float* ln_b = (const float*)d_in[23];
    const float* Wpos = (const float*)d_in[24];
    const float* Wres = (const float*)d_in[25];
    const float* bres = (const float*)d_in[26];
    float* out = (float*)d_out;

    float *pq, *pcn, *ph, *pt1, *pt2, *pt3, *pkv, *paw, *psf, *pwp;
    int *ptok, *prm;
    cudaGetSymbolAddress((void**)&pq,  g_q);
    cudaGetSymbolAddress((void**)&pcn, g_cn);
    cudaGetSymbolAddress((void**)&ph,  g_h);
    cudaGetSymbolAddress((void**)&pt1, g_t1);
    cudaGetSymbolAddress((void**)&pt2, g_t2);
    cudaGetSymbolAddress((void**)&pt3, g_t3);
    cudaGetSymbolAddress((void**)&pkv, g_kv);
    cudaGetSymbolAddress((void**)&paw, g_aw);
    cudaGetSymbolAddress((void**)&psf, g_sf);
    cudaGetSymbolAddress((void**)&pwp, g_wp);
    cudaGetSymbolAddress((void**)&ptok, g_tok);
    cudaGetSymbolAddress((void**)&prm,  g_rm);

    // prologue
    rowmap_kernel<<<BKV/256, 256>>>(kidx, prm);
    argmax_tok<<<BN/8, 256>>>(a2t, ptok);
    sgemm<<<dim3(1, (Bb*Tt)/128), 256>>>(a, a2q, paw, Bb*Tt, 128, Ss, nullptr);
    addaw_kernel<<<(BN*32)/256, 256>>>(qin, paw, ptok, pq);
    ln_rows<<<BN/8, 256>>>(c, pcn);

    // weight packing (per layer): [cs|cb], [q|g], [k|v], [cs2|cb2], [W1|W2]
    for (int l = 0; l < Ll; l++) {
        float* wl = pwp + l*PL;
        pack2<<<256, 256>>>(Wcs  + l*Dd*Dd, Wcb  + l*Dd*Dd, wl,          Dd, Dd, Dd);
        pack2<<<256, 256>>>(Wq   + l*Dd*Dd, Wg   + l*Dd*Dd, wl +  32768, Dd, Dd, Dd);
        pack2<<<256, 256>>>(Wk   + l*Dd*Dd, Wv   + l*Dd*Dd, wl +  65536, Dd, Dd, Dd);
        pack2<<<256, 256>>>(Wcs2 + l*Dd*Dd, Wcb2 + l*Dd*Dd, wl +  98304, Dd, Dd, Dd);
        pack2<<<256, 256>>>(W1 + l*Dd*256,  W2 + l*Dd*256,  wl + 131072, Dd, 256, 256);
    }

    for (int l = 0; l < Ll; l++) {
        const float* wl = pwp + l*PL;
        // hcur = ln(q)*sig(cn@Wcs) + cn@Wcb
        sgemm<<<dim3(2, BN/128), 256>>>(pcn, wl, pt1, BN, 256, Dd, nullptr);
        ew_hcur<<<BN/8, 256>>>(pq, pt1, ph);
        // Q|G projection
        sgemm<<<dim3(2, BN/128), 256>>>(ph, wl + 32768, pt2, BN, 256, Dd, nullptr);
        // gathered K|V projection
        sgemm<<<dim3(2, BKV/128), 256>>>(ph, wl + 65536, pkv, BKV, 256, Dd, prm);
        // attention (+ sigmoid(Wg) gate)
        attn_kernel<<<dim3(NHh, NWw, Bb), 128>>>(pkv, pt2, bias, mask, kidx, pt3);
        // q += sig(cn@Wog) * (o@Wo)
        sgemm<<<dim3(1, BN/128), 256>>>(pt3, Wo + l*Dd*Dd, pt1, BN, Dd, Dd, nullptr);
        sgemm<<<dim3(1, BN/128), 256>>>(pcn, Wog + l*Dd*Dd, pt2, BN, Dd, Dd, nullptr);
        ew_resid<<<(BN*32)/256, 256>>>(pq, pt2, pt1);
        // h2 = ln(q)*sig(cn@Wcs2) + cn@Wcb2
        sgemm<<<dim3(2, BN/128), 256>>>(pcn, wl + 98304, pt1, BN, 256, Dd, nullptr);
        ew_hcur<<<BN/8, 256>>>(pq, pt1, ph);
        // FFN: silu(h2@W1)*(h2@W2) @ W3, gated by sig(cn@Wog2)
        sgemm<<<dim3(4, BN/128), 256>>>(ph, wl + 131072, pkv, BN, 512, Dd, nullptr);
        ew_glu<<<(BN*64)/256, 256>>>(pkv, pt1);
        sgemm<<<dim3(1, BN/128), 256>>>(pt1, W3 + l*256*Dd, pt2, BN, Dd, 256, nullptr);
        sgemm<<<dim3(1, BN/128), 256>>>(pcn, Wog2 + l*Dd*Dd, pt3, BN, Dd, Dd, nullptr);
        ew_resid<<<(BN*32)/256, 256>>>(pq, pt3, pt2);
    }

    // epilogue: segment-sum -> res_type ; ln(q)*g+b @ Wpos -> r_update
    cudaMemsetAsync(psf, 0, (size_t)Bb*Tt*Dd*sizeof(float));
    sfeat_kernel<<<(BN*128)/256, 256>>>(pq, mask, ptok, psf);
    restype_kernel<<<Bb*Tt, 128>>>(psf, Wres, bres, out + (size_t)BN*3);
    rupdate_kernel<<<BN, 128>>>(pq, ln_g, ln_b, Wpos, out);
}

// round 4
// speedup vs baseline: 1.3227x; 1.3227x over previous
#include <cuda_runtime.h>
#include <cuda_bf16.h>
#include <cstdint>

#define Bb   2
#define Nn   16384
#define Tt   2048
#define Dd   128
#define Ss   384
#define NWw  512
#define WQq  32
#define Hh   128
#define Ll   3
#define NHh  4
#define NTOKk 33
#define BN   (Bb*Nn)          // 32768
#define BKV  (Bb*NWw*Hh)      // 131072
#define PL2  278528           // packed weights per layer (floats)

// ---------------- scratch (device globals; allocation-free) ----------------
__device__ float g_q   [BN*Dd];
__device__ float g_cn  [BN*Dd];
__device__ float g_h   [BN*Dd];
__device__ float g_t1  [BN*256];
__device__ float g_t2  [BN*256];
__device__ float g_t3  [BN*Dd];
__device__ float g_kv  [(size_t)BKV*256];     // also reused for FFN (BN*512 fits)
__device__ float g_cng [(size_t)BN*768];      // cn @ [cs|cb|og|cs2|cb2|og2]
__device__ float g_aw  [Bb*Tt*Dd];
__device__ float g_sf  [Bb*Tt*Dd];
__device__ float g_wp  [Ll*PL2 + 49152];
__device__ int   g_tok [BN];
__device__ int   g_rm  [BKV];

__device__ __forceinline__ float sigf(float x){ return 1.f/(1.f + __expf(-x)); }

// ---------------- mma.sync bf16 GEMM --------------------------------------
// C[M,Ntot] = A[M,Ktot] @ Bt[Ntot,Ktot]^T, fp32 in/out.
// bf16 hi/lo 3-pass split: D = Ah@Bh + Ah@Bl + Al@Bh (fp32 reg accumulate).
// Tile 128x128, 8 warps of 32x64, K-chunk 64, smem stride 72 (conflict-free).
#define KC      64
#define ASTRIDE 72
#define OPELEMS (128*ASTRIDE)           // 9216 bf16 per operand buffer
#define GEMM_SMEM (4*OPELEMS*2)         // 73728 bytes

__device__ __forceinline__ void mma16816(float* d, const uint32_t* a,
                                         uint32_t b0, uint32_t b1){
    asm volatile(
        "mma.sync.aligned.m16n8k16.row.col.f32.bf16.bf16.f32 "
        "{%0,%1,%2,%3}, {%4,%5,%6,%7}, {%8,%9}, {%0,%1,%2,%3};"
        : "+f"(d[0]), "+f"(d[1]), "+f"(d[2]), "+f"(d[3])
        : "r"(a[0]), "r"(a[1]), "r"(a[2]), "r"(a[3]), "r"(b0), "r"(b1));
}

__global__ __launch_bounds__(256) void gemm_tc(
    const float* __restrict__ A, const float* __restrict__ Bt,
    float* __restrict__ C, int Ntot, int Ktot, const int* __restrict__ rowmap)
{
    extern __shared__ __nv_bfloat16 smb[];
    __nv_bfloat16* const Ah = smb;                 // lo buffers at +OPELEMS
    __nv_bfloat16* const Bh = smb + 2*OPELEMS;
    const int tid = threadIdx.x, wid = tid >> 5, lane = tid & 31;
    const int m0 = blockIdx.y << 7, n0 = blockIdx.x << 7;

    // each thread owns one smem row of one operand
    const int lrow = tid & 127;
    const float* src;
    __nv_bfloat16* dsth;
    if (tid < 128) {
        int r = m0 + lrow;
        if (rowmap) r = rowmap[r];
        src = A + (size_t)r * Ktot;
        dsth = Ah + lrow*ASTRIDE;
    } else {
        src = Bt + (size_t)(n0 + lrow) * Ktot;
        dsth = Bh + lrow*ASTRIDE;
    }

    const int wm = (wid & 3) << 5;     // warp m-offset (0,32,64,96)
    const int wn = (wid >> 2) << 6;    // warp n-offset (0,64)
    const int l4 = (lane & 3) << 1, lq = lane >> 2;

    float acc[2][8][4];
#pragma unroll
    for (int i = 0; i < 2; i++)
#pragma unroll
        for (int j = 0; j < 8; j++)
#pragma unroll
            for (int k = 0; k < 4; k++) acc[i][j][k] = 0.f;

    for (int kc = 0; kc < Ktot; kc += KC) {
        // fp32 -> bf16 hi/lo convert + store
#pragma unroll
        for (int j = 0; j < 16; j++) {
            float4 v = *(const float4*)(src + kc + j*4);
            __nv_bfloat162 h01 = __floats2bfloat162_rn(v.x, v.y);
            __nv_bfloat162 h23 = __floats2bfloat162_rn(v.z, v.w);
            float2 f01 = __bfloat1622float2(h01);
            float2 f23 = __bfloat1622float2(h23);
            __nv_bfloat162 l01 = __floats2bfloat162_rn(v.x - f01.x, v.y - f01.y);
            __nv_bfloat162 l23 = __floats2bfloat162_rn(v.z - f23.x, v.w - f23.y);
            *(uint2*)(dsth + j*4) =
                make_uint2(*(uint32_t*)&h01, *(uint32_t*)&h23);
            *(uint2*)(dsth + OPELEMS + j*4) =
                make_uint2(*(uint32_t*)&l01, *(uint32_t*)&l23);
        }
        __syncthreads();

#pragma unroll
        for (int pass = 0; pass < 3; pass++) {
            const __nv_bfloat16* Ap = Ah + ((pass == 2) ? OPELEMS : 0);
            const __nv_bfloat16* Bp = Bh + ((pass == 1) ? OPELEMS : 0);
#pragma unroll
            for (int ks = 0; ks < KC/16; ks++) {
                const int k0 = ks*16;
                uint32_t af[2][4];
#pragma unroll
                for (int mt = 0; mt < 2; mt++) {
                    const __nv_bfloat16* p = Ap + (wm + mt*16 + lq)*ASTRIDE + k0 + l4;
                    af[mt][0] = *(const uint32_t*)(p);
                    af[mt][1] = *(const uint32_t*)(p + 8*ASTRIDE);
                    af[mt][2] = *(const uint32_t*)(p + 8);
                    af[mt][3] = *(const uint32_t*)(p + 8*ASTRIDE + 8);
                }
#pragma unroll
                for (int nt = 0; nt < 8; nt++) {
                    const __nv_bfloat16* p = Bp + (wn + nt*8 + lq)*ASTRIDE + k0 + l4;
                    uint32_t b0 = *(const uint32_t*)(p);
                    uint32_t b1 = *(const uint32_t*)(p + 8);
                    mma16816(acc[0][nt], af[0], b0, b1);
                    mma16816(acc[1][nt], af[1], b0, b1);
                }
            }
        }
        __syncthreads();
    }

    // epilogue: register accumulators -> C
#pragma unroll
    for (int mt = 0; mt < 2; mt++) {
        int r = m0 + wm + mt*16 + lq;
        float* cp0 = C + (size_t)r*Ntot + n0 + wn + l4;
        float* cp1 = cp0 + (size_t)8*Ntot;
#pragma unroll
        for (int nt = 0; nt < 8; nt++) {
            *(float2*)(cp0 + nt*8) = make_float2(acc[mt][nt][0], acc[mt][nt][1]);
            *(float2*)(cp1 + nt*8) = make_float2(acc[mt][nt][2], acc[mt][nt][3]);
        }
    }
}

// ---------------- attention: one block per (head, window, batch) ------------
__global__ __launch_bounds__(128) void attn_kernel(
    const float* __restrict__ kv, const float* __restrict__ qg,
    const float* __restrict__ bias, const float* __restrict__ mask,
    const int* __restrict__ kidx, float* __restrict__ obuf)
{
    __shared__ float qs[32*33];
    __shared__ float ks[128*33];
    __shared__ float sc[32*129];
    __shared__ float mv[128];
    const int t  = threadIdx.x;
    const int hd = blockIdx.x, w = blockIdx.y, b = blockIdx.z;
    const size_t kvbase = ((size_t)(b*NWw + w) * Hh) * 256 + hd*32;
    const size_t qbase  = ((size_t)(b*Nn + w*WQq)) * 256 + hd*32;

#pragma unroll
    for (int i = 0; i < 8; i++) {
        int s = t + i*128; int qq = s >> 5, d = s & 31;
        qs[qq*33 + d] = qg[qbase + (size_t)qq*256 + d];
    }
#pragma unroll
    for (int i = 0; i < 32; i++) {
        int s = t + i*128; int kk = s >> 5, d = s & 31;
        ks[kk*33 + d] = kv[kvbase + (size_t)kk*256 + d];
    }
    {
        int ki = kidx[w*Hh + t];
        mv[t] = (1.0f - mask[b*Nn + ki]) * -1e9f;
    }
    __syncthreads();

    const float* bptr = bias + ((((size_t)b*NWw + w)*NHh + hd)*WQq)*Hh + t;
    const float mvt = mv[t];
#pragma unroll 4
    for (int qq = 0; qq < 32; qq++) {
        float a = 0.f;
#pragma unroll
        for (int d = 0; d < 32; d++) a += qs[qq*33 + d]*ks[t*33 + d];
        sc[qq*129 + t] = a*0.17677669529663689f + bptr[(size_t)qq*Hh] + mvt;
    }
    __syncthreads();

#pragma unroll
    for (int i = 0; i < 32; i++) {
        int s = t + i*128; int kk = s >> 5, d = s & 31;
        ks[kk*33 + d] = kv[kvbase + (size_t)kk*256 + 128 + d];
    }
    {
        int qq = t >> 2, seg = t & 3;
        float* row = sc + qq*129 + seg*32;
        float mx = -1e30f;
#pragma unroll
        for (int j = 0; j < 32; j++) mx = fmaxf(mx, row[j]);
        mx = fmaxf(mx, __shfl_xor_sync(0xffffffffu, mx, 1));
        mx = fmaxf(mx, __shfl_xor_sync(0xffffffffu, mx, 2));
        float sum = 0.f;
#pragma unroll
        for (int j = 0; j < 32; j++) { float e = __expf(row[j]-mx); row[j] = e; sum += e; }
        sum += __shfl_xor_sync(0xffffffffu, sum, 1);
        sum += __shfl_xor_sync(0xffffffffu, sum, 2);
        float inv = 1.f/sum;
#pragma unroll
        for (int j = 0; j < 32; j++) row[j] *= inv;
    }
    __syncthreads();

    {
        int qq = t >> 2, ds = (t & 3) * 8;
        float acc[8];
#pragma unroll
        for (int j = 0; j < 8; j++) acc[j] = 0.f;
#pragma unroll 8
        for (int k = 0; k < 128; k++) {
            float s = sc[qq*129 + k];
#pragma unroll
            for (int j = 0; j < 8; j++) acc[j] += s*ks[k*33 + ds + j];
        }
        size_t nrow = (size_t)(b*Nn + w*WQq + qq);
#pragma unroll
        for (int j = 0; j < 8; j++) {
            float g = qg[nrow*256 + 128 + hd*32 + ds + j];
            obuf[nrow*128 + hd*32 + ds + j] = acc[j] * sigf(g);
        }
    }
}

// ---------------- elementwise / small kernels ----------------
__global__ void ln_rows(const float* __restrict__ x, float* __restrict__ y) {
    int warp = threadIdx.x >> 5, lane = threadIdx.x & 31;
    size_t row = (size_t)blockIdx.x*8 + warp;
    float4 v = *(const float4*)(x + row*128 + lane*4);
    float s  = v.x+v.y+v.z+v.w;
    float ss = v.x*v.x+v.y*v.y+v.z*v.z+v.w*v.w;
#pragma unroll
    for (int o = 16; o; o >>= 1) { s += __shfl_xor_sync(~0u, s, o); ss += __shfl_xor_sync(~0u, ss, o); }
    float m = s*(1.f/128.f);
    float rstd = rsqrtf(ss*(1.f/128.f) - m*m + 1e-5f);
    float4 r;
    r.x = (v.x-m)*rstd; r.y = (v.y-m)*rstd; r.z = (v.z-m)*rstd; r.w = (v.w-m)*rstd;
    *(float4*)(y + row*128 + lane*4) = r;
}

// h = ln(q) * sigmoid(X[:, 0:128]) + X[:, 128:256]  (X row stride = xs)
__global__ void ew_hcur(const float* __restrict__ q, const float* __restrict__ X,
                        int xs, float* __restrict__ h) {
    int warp = threadIdx.x >> 5, lane = threadIdx.x & 31;
    size_t row = (size_t)blockIdx.x*8 + warp;
    float4 v = *(const float4*)(q + row*128 + lane*4);
    float s  = v.x+v.y+v.z+v.w;
    float ss = v.x*v.x+v.y*v.y+v.z*v.z+v.w*v.w;
#pragma unroll
    for (int o = 16; o; o >>= 1) { s += __shfl_xor_sync(~0u, s, o); ss += __shfl_xor_sync(~0u, ss, o); }
    float m = s*(1.f/128.f);
    float rstd = rsqrtf(ss*(1.f/128.f) - m*m + 1e-5f);
    float4 g  = *(const float4*)(X + row*xs + lane*4);
    float4 bb = *(const float4*)(X + row*xs + 128 + lane*4);
    float4 r;
    r.x = (v.x-m)*rstd*sigf(g.x) + bb.x;
    r.y = (v.y-m)*rstd*sigf(g.y) + bb.y;
    r.z = (v.z-m)*rstd*sigf(g.z) + bb.z;
    r.w = (v.w-m)*rstd*sigf(g.w) + bb.w;
    *(float4*)(h + row*128 + lane*4) = r;
}

// q += sigmoid(gate) * x   (gate row stride = gs)
__global__ void ew_resid(float* __restrict__ q, const float* __restrict__ gate,
                         int gs, const float* __restrict__ x) {
    size_t i4 = (size_t)blockIdx.x*blockDim.x + threadIdx.x;   // BN*32 total
    size_t row = i4 >> 5;
    int c4 = (int)(i4 & 31) << 2;
    float4 qq = *(float4*)(q + i4*4);
    float4 g  = *(const float4*)(gate + row*gs + c4);
    float4 xx = *(const float4*)(x + i4*4);
    qq.x += sigf(g.x)*xx.x; qq.y += sigf(g.y)*xx.y;
    qq.z += sigf(g.z)*xx.z; qq.w += sigf(g.w)*xx.w;
    *(float4*)(q + i4*4) = qq;
}

__global__ void ew_glu(const float* __restrict__ T, float* __restrict__ out) {
    size_t i4 = (size_t)blockIdx.x*blockDim.x + threadIdx.x;   // BN*64 total
    size_t row = i4 >> 6;
    int c4 = (int)(i4 & 63) << 2;
    float4 a  = *(const float4*)(T + row*512 + c4);
    float4 bb = *(const float4*)(T + row*512 + 256 + c4);
    float4 r;
    r.x = a.x*sigf(a.x)*bb.x; r.y = a.y*sigf(a.y)*bb.y;
    r.z = a.z*sigf(a.z)*bb.z; r.w = a.w*sigf(a.w)*bb.w;
    *(float4*)(out + row*256 + c4) = r;
}

// one-shot transpose-pack of all weights into g_wp
__global__ void pack_all(
    const float* __restrict__ Wcs,  const float* __restrict__ Wcb,
    const float* __restrict__ Wog,  const float* __restrict__ Wcs2,
    const float* __restrict__ Wcb2, const float* __restrict__ Wog2,
    const float* __restrict__ Wq,   const float* __restrict__ Wg,
    const float* __restrict__ Wk,   const float* __restrict__ Wv,
    const float* __restrict__ W1,   const float* __restrict__ W2,
    const float* __restrict__ Wo,   const float* __restrict__ W3,
    const float* __restrict__ a2q,  float* __restrict__ dst)
{
    const int total = Ll*PL2 + 49152;
    for (int i = blockIdx.x*blockDim.x + threadIdx.x; i < total; i += gridDim.x*blockDim.x) {
        float v;
        if (i >= Ll*PL2) {                       // a2q^T : [128,384]
            int r = i - Ll*PL2;
            int n = r / 384, k = r % 384;
            v = a2q[k*128 + n];
        } else {
            int l = i / PL2, o = i % PL2;
            if (o < 98304) {                     // cn block: 6 square mats
                int m = o >> 14, r = o & 16383;
                int n = r >> 7, k = r & 127;
                const float* S = (m==0)?Wcs:(m==1)?Wcb:(m==2)?Wog:(m==3)?Wcs2:(m==4)?Wcb2:Wog2;
                v = S[l*16384 + k*128 + n];
            } else if (o < 131072) {             // [Wq|Wg]
                int r = o - 98304;
                int n = r >> 7, k = r & 127;
                v = (n < 128) ? Wq[l*16384 + k*128 + n] : Wg[l*16384 + k*128 + n-128];
            } else if (o < 163840) {             // [Wk|Wv]
                int r = o - 131072;
                int n = r >> 7, k = r & 127;
                v = (n < 128) ? Wk[l*16384 + k*128 + n] : Wv[l*16384 + k*128 + n-128];
            } else if (o < 229376) {             // [W1|W2]^T : [512,128]
                int r = o - 163840;
                int n = r >> 7, k = r & 127;
                v = (n < 256) ? W1[l*32768 + k*256 + n] : W2[l*32768 + k*256 + n-256];
            } else if (o < 245760) {             // Wo^T
                int r = o - 229376;
                int n = r >> 7, k = r & 127;
                v = Wo[l*16384 + k*128 + n];
            } else {                             // W3^T : [128,256]
                int r = o - 245760;
                int n = r >> 8, k = r & 255;
                v = W3[l*32768 + k*128 + n];
            }
        }
        dst[i] = v;
    }
}

__global__ void rowmap_kernel(const int* __restrict__ kidx, int* __restrict__ rm) {
    int i = blockIdx.x*256 + threadIdx.x;
    int b = i / (NWw*Hh);
    int r = i % (NWw*Hh);
    rm[i] = b*Nn + kidx[r];
}

__global__ void argmax_tok(const float* __restrict__ a2t, int* __restrict__ tok) {
    int warp = threadIdx.x >> 5, lane = threadIdx.x & 31;
    size_t row = (size_t)blockIdx.x*8 + warp;
    const float* p = a2t + row*Tt;
    float bv = -1e30f; int bi = 0;
    for (int j = lane; j < Tt; j += 32) { float v = p[j]; if (v > bv) { bv = v; bi = j; } }
#pragma unroll
    for (int o = 16; o; o >>= 1) {
        float ov = __shfl_xor_sync(~0u, bv, o);
        int   oi = __shfl_xor_sync(~0u, bi, o);
        if (ov > bv || (ov == bv && oi < bi)) { bv = ov; bi = oi; }
    }
    if (lane == 0) tok[row] = bi;
}

__global__ void addaw_kernel(const float* __restrict__ qin, const float* __restrict__ aw,
                             const int* __restrict__ tok, float* __restrict__ q) {
    size_t i4 = (size_t)blockIdx.x*256 + threadIdx.x;
    int row = (int)(i4 >> 5);
    int d4  = (int)(i4 & 31) << 2;
    int b = row >> 14;
    int t = tok[row];
    float4 v = *(const float4*)(qin + ((size_t)row << 7) + d4);
    float4 w = *(const float4*)(aw + (((size_t)b*Tt + t) << 7) + d4);
    v.x += w.x; v.y += w.y; v.z += w.z; v.w += w.w;
    *(float4*)(q + ((size_t)row << 7) + d4) = v;
}

__global__ void sfeat_kernel(const float* __restrict__ q, const float* __restrict__ mask,
                             const int* __restrict__ tok, float* __restrict__ sf) {
    size_t e = (size_t)blockIdx.x*256 + threadIdx.x;
    int row = (int)(e >> 7);
    int d = (int)(e & 127);
    int b = row >> 14;
    int t = tok[row];
    atomicAdd(&sf[(((size_t)b*Tt + t) << 7) + d], q[e]*mask[row]);
}

__global__ __launch_bounds__(128) void restype_kernel(
    const float* __restrict__ sf, const float* __restrict__ Wres,
    const float* __restrict__ bres, float* __restrict__ out) {
    __shared__ float sr[128];
    int t = threadIdx.x;
    size_t row = blockIdx.x;
    sr[t] = sf[row*128 + t];
    __syncthreads();
    if (t < NTOKk) {
        float acc = bres[t];
#pragma unroll 16
        for (int d = 0; d < 128; d++) acc += sr[d]*Wres[d*NTOKk + t];
        out[row*NTOKk + t] = acc;
    }
}

__global__ __launch_bounds__(128) void rupdate_kernel(
    const float* __restrict__ q, const float* __restrict__ g,
    const float* __restrict__ bb, const float* __restrict__ Wpos,
    float* __restrict__ out) {
    __shared__ float r1[128], r2[128];
    __shared__ float ms, rs;
    int d = threadIdx.x;
    size_t row = blockIdx.x;
    float x = q[row*128 + d];
    r1[d] = x; r2[d] = x*x;
    __syncthreads();
    for (int o = 64; o; o >>= 1) { if (d < o) { r1[d] += r1[d+o]; r2[d] += r2[d+o]; } __syncthreads(); }
    if (d == 0) {
        float m = r1[0]*(1.f/128.f);
        float v = r2[0]*(1.f/128.f) - m*m;
        ms = m; rs = rsqrtf(v + 1e-5f);
    }
    __syncthreads();
    float y = (x - ms)*rs*g[d] + bb[d];
    float p0 = y*Wpos[d*3], p1 = y*Wpos[d*3+1], p2 = y*Wpos[d*3+2];
    r1[d] = p0; r2[d] = p1;
    __syncthreads();
    for (int o = 64; o; o >>= 1) { if (d < o) { r1[d] += r1[d+o]; r2[d] += r2[d+o]; } __syncthreads(); }
    if (d == 0) { out[row*3] = r1[0]; out[row*3+1] = r2[0]; }
    __syncthreads();
    r1[d] = p2;
    __syncthreads();
    for (int o = 64; o; o >>= 1) { if (d < o) { r1[d] += r1[d+o]; } __syncthreads(); }
    if (d == 0) out[row*3+2] = r1[0];
}

// ---------------- host launcher ----------------
extern "C" void kernel_launch(void* const* d_in, const int* in_sizes, int n_in,
                              void* d_out, int out_size) {
    (void)in_sizes; (void)n_in; (void)out_size;
    const float* a    = (const float*)d_in[0];
    const float* qin  = (const float*)d_in[1];
    const float* c    = (const float*)d_in[2];
    const float* bias = (const float*)d_in[3];
    const float* a2t  = (const float*)d_in[4];
    const float* mask = (const float*)d_in[5];
    const int*   kidx = (const int*)  d_in[6];
    const float* a2q  = (const float*)d_in[7];
    const float* Wq   = (const float*)d_in[8];
    const float* Wk   = (const float*)d_in[9];
    const float* Wv   = (const float*)d_in[10];
    const float* Wg   = (const float*)d_in[11];
    const float* Wo   = (const float*)d_in[12];
    const float* Wcs  = (const float*)d_in[13];
    const float* Wcb  = (const float*)d_in[14];
    const float* Wog  = (const float*)d_in[15];
    const float* Wcs2 = (const float*)d_in[16];
    const float* Wcb2 = (const float*)d_in[17];
    const float* Wog2 = (const float*)d_in[18];
    const float* W1   = (const float*)d_in[19];
    const float* W2   = (const float*)d_in[20];
    const float* W3   = (const float*)d_in[21];
    const float* ln_g = (const float*)d_in[22];
    const float* ln_b = (const float*)d_in[23];
    const float* Wpos = (const float*)d_in[24];
    const float* Wres = (const float*)d_in[25];
    const float* bres = (const float*)d_in[26];
    float* out = (float*)d_out;

    float *pq, *pcn, *ph, *pt1, *pt2, *pt3, *pkv, *pcng, *paw, *psf, *pwp;
    int *ptok, *prm;
    cudaGetSymbolAddress((void**)&pq,   g_q);
    cudaGetSymbolAddress((void**)&pcn,  g_cn);
    cudaGetSymbolAddress((void**)&ph,   g_h);
    cudaGetSymbolAddress((void**)&pt1,  g_t1);
    cudaGetSymbolAddress((void**)&pt2,  g_t2);
    cudaGetSymbolAddress((void**)&pt3,  g_t3);
    cudaGetSymbolAddress((void**)&pkv,  g_kv);
    cudaGetSymbolAddress((void**)&pcng, g_cng);
    cudaGetSymbolAddress((void**)&paw,  g_aw);
    cudaGetSymbolAddress((void**)&psf,  g_sf);
    cudaGetSymbolAddress((void**)&pwp,  g_wp);
    cudaGetSymbolAddress((void**)&ptok, g_tok);
    cudaGetSymbolAddress((void**)&prm,  g_rm);

    cudaFuncSetAttribute(gemm_tc, cudaFuncAttributeMaxDynamicSharedMemorySize, GEMM_SMEM);

    // prologue
    pack_all<<<512, 256>>>(Wcs, Wcb, Wog, Wcs2, Wcb2, Wog2, Wq, Wg, Wk, Wv,
                           W1, W2, Wo, W3, a2q, pwp);
    rowmap_kernel<<<BKV/256, 256>>>(kidx, prm);
    argmax_tok<<<BN/8, 256>>>(a2t, ptok);
    gemm_tc<<<dim3(1, (Bb*Tt)/128), 256, GEMM_SMEM>>>(a, pwp + Ll*PL2, paw, 128, Ss, nullptr);
    addaw_kernel<<<(BN*32)/256, 256>>>(qin, paw, ptok, pq);
    ln_rows<<<BN/8, 256>>>(c, pcn);

    for (int l = 0; l < Ll; l++) {
        const float* wl = pwp + l*PL2;
        // all six cn projections at once: [cs|cb|og|cs2|cb2|og2]
        gemm_tc<<<dim3(6, BN/128), 256, GEMM_SMEM>>>(pcn, wl, pcng, 768, Dd, nullptr);
        // hcur = ln(q)*sig(cs) + cb
        ew_hcur<<<BN/8, 256>>>(pq, pcng, 768, ph);
        // Q|G projection
        gemm_tc<<<dim3(2, BN/128), 256, GEMM_SMEM>>>(ph, wl + 98304, pt2, 256, Dd, nullptr);
        // gathered K|V projection
        gemm_tc<<<dim3(2, BKV/128), 256, GEMM_SMEM>>>(ph, wl + 131072, pkv, 256, Dd, prm);
        // attention (+ sigmoid(Wg) gate)
        attn_kernel<<<dim3(NHh, NWw, Bb), 128>>>(pkv, pt2, bias, mask, kidx, pt3);
        // q += sig(og) * (o@Wo)
        gemm_tc<<<dim3(1, BN/128), 256, GEMM_SMEM>>>(pt3, wl + 229376, pt1, 128, Dd, nullptr);
        ew_resid<<<(BN*32)/256, 256>>>(pq, pcng + 256, 768, pt1);
        // h2 = ln(q)*sig(cs2) + cb2
        ew_hcur<<<BN/8, 256>>>(pq, pcng + 384, 768, ph);
        // FFN
        gemm_tc<<<dim3(4, BN/128), 256, GEMM_SMEM>>>(ph, wl + 163840, pkv, 512, Dd, nullptr);
        ew_glu<<<(BN*64)/256, 256>>>(pkv, pt1);
        gemm_tc<<<dim3(1, BN/128), 256, GEMM_SMEM>>>(pt1, wl + 245760, pt2, 128, 256, nullptr);
        ew_resid<<<(BN*32)/256, 256>>>(pq, pcng + 640, 768, pt2);
    }

    // epilogue
    cudaMemsetAsync(psf, 0, (size_t)Bb*Tt*Dd*sizeof(float));
    sfeat_kernel<<<(BN*128)/256, 256>>>(pq, mask, ptok, psf);
    restype_kernel<<<Bb*Tt, 128>>>(psf, Wres, bres, out + (size_t)BN*3);
    rupdate_kernel<<<BN, 128>>>(pq, ln_g, ln_b, Wpos, out);
}

// round 5
// speedup vs baseline: 1.4836x; 1.1217x over previous
#include <cuda_runtime.h>
#include <cuda_bf16.h>
#include <cstdint>

#define Bb   2
#define Nn   16384
#define Tt   2048
#define Dd   128
#define Ss   384
#define NWw  512
#define WQq  32
#define Hh   128
#define Ll   3
#define NHh  4
#define NTOKk 33
#define BN   (Bb*Nn)          // 32768
#define BKV  (Bb*NWw*Hh)      // 131072
#define PL2  278528           // packed weight floats per layer (bf16 = 2x)

// ---------------- scratch (device globals; allocation-free) ----------------
__device__ __align__(256) float g_q   [BN*Dd];
__device__ __align__(256) __nv_bfloat16 g_cn [BN*256];     // ln(c) hi|lo
__device__ __align__(256) __nv_bfloat16 g_h  [BN*256];     // hcur hi|lo
__device__ __align__(256) __nv_bfloat16 g_t3 [BN*256];     // attn out hi|lo
__device__ __align__(256) float g_t1  [BN*256];
__device__ __align__(256) float g_t2  [BN*256];
__device__ __align__(256) float g_kv  [(size_t)BKV*256];   // reused for FFN out
__device__ __align__(256) float g_cng [(size_t)BN*768];    // cn gates; also a_cvt
__device__ __align__(256) float g_aw  [Bb*Tt*Dd];
__device__ __align__(256) float g_sf  [Bb*Tt*Dd];
__device__ __align__(256) __nv_bfloat16 g_wp [2*(Ll*PL2 + 49152)];
__device__ int g_tok[BN];
__device__ int g_rm [BKV];

__device__ __forceinline__ float sigf(float x){ return 1.f/(1.f + __expf(-x)); }

__device__ __forceinline__ uint32_t s2u(const void* p){
    uint32_t a;
    asm("{ .reg .u64 t; cvta.to.shared.u64 t, %1; cvt.u32.u64 %0, t; }" : "=r"(a) : "l"(p));
    return a;
}

// ---------------- bf16 mma.sync GEMM with cp.async + ldmatrix --------------
// A[M,2K] bf16 (hi|lo rows), Bt[N,2K] bf16. C[M,N] fp32.
// D = Ah@Bh + Ah@Bl + Al@Bh, fp32 register accumulate.
// Tile 128x128, 8 warps of 32x64, K-chunk 64, 2-stage pipeline.
#define AS       72
#define CHUNK_E  (128*AS)            // 9216 bf16 per sub-buffer
#define CHUNK_B  (CHUNK_E*2)         // bytes
#define STAGE_B  (4*CHUNK_B)         // [Ahi][Alo][Bhi][Blo] = 73728 bytes
#define GEMM_SMEM (2*STAGE_B)        // 147456 bytes

__device__ __forceinline__ void mma16816(float* d, const uint32_t* a,
                                         uint32_t b0, uint32_t b1){
    asm volatile(
        "mma.sync.aligned.m16n8k16.row.col.f32.bf16.bf16.f32 "
        "{%0,%1,%2,%3}, {%4,%5,%6,%7}, {%8,%9}, {%0,%1,%2,%3};"
        : "+f"(d[0]), "+f"(d[1]), "+f"(d[2]), "+f"(d[3])
        : "r"(a[0]), "r"(a[1]), "r"(a[2]), "r"(a[3]), "r"(b0), "r"(b1));
}
__device__ __forceinline__ void ldsm4(uint32_t* r, uint32_t a){
    asm volatile("ldmatrix.sync.aligned.m8n8.x4.shared.b16 {%0,%1,%2,%3}, [%4];"
        : "=r"(r[0]), "=r"(r[1]), "=r"(r[2]), "=r"(r[3]) : "r"(a));
}
__device__ __forceinline__ void cpa16(uint32_t d, const void* s){
    asm volatile("cp.async.cg.shared.global [%0], [%1], 16;" :: "r"(d), "l"(s));
}

__global__ __launch_bounds__(256) void gemm_tc(
    const __nv_bfloat16* __restrict__ A, const __nv_bfloat16* __restrict__ Bt,
    float* __restrict__ C, int Ntot, int Ktot, const int* __restrict__ rowmap)
{
    extern __shared__ __nv_bfloat16 smb[];
    const uint32_t smbase = s2u(smb);
    const int tid = threadIdx.x, wid = tid >> 5, lane = tid & 31;
    const int m0 = blockIdx.y << 7, n0 = blockIdx.x << 7;

    // loader role: threads 0-127 -> A rows, 128-255 -> B rows
    const int lrow = tid & 127;
    const __nv_bfloat16* src;
    uint32_t dstoff;
    if (tid < 128) {
        int r = m0 + lrow;
        if (rowmap) r = rowmap[r];
        src = A + (size_t)r * (2*Ktot);
        dstoff = (uint32_t)(lrow*AS)*2u;
    } else {
        src = Bt + (size_t)(n0 + lrow) * (2*Ktot);
        dstoff = (uint32_t)(2*CHUNK_E + lrow*AS)*2u;
    }

    const int wm = (wid & 3) << 5;     // 0,32,64,96
    const int wn = (wid >> 2) << 6;    // 0,64

    // ldmatrix per-thread byte offsets (within Ahi / Bhi regions)
    const int rA = wm + ((lane>>3)&1)*8 + (lane&7);
    const int cA = (lane>>4)*8;
    const uint32_t aoff0 = (uint32_t)(rA*AS + cA)*2u;
    const uint32_t aoff1 = aoff0 + 16*AS*2u;
    const int rB = wn + (lane>>4)*8 + (lane&7);
    const int cB = ((lane>>3)&1)*8;
    const uint32_t boff0 = (uint32_t)(rB*AS + cB)*2u;

    float acc[2][8][4];
#pragma unroll
    for (int i = 0; i < 2; i++)
#pragma unroll
        for (int j = 0; j < 8; j++)
#pragma unroll
            for (int k = 0; k < 4; k++) acc[i][j][k] = 0.f;

    const int nch = Ktot >> 6;

    // issue chunk 0
    {
        uint32_t d = smbase + dstoff;
        const __nv_bfloat16* gh = src;
        const __nv_bfloat16* gl = src + Ktot;
#pragma unroll
        for (int j = 0; j < 8; j++) cpa16(d + j*16, gh + j*8);
#pragma unroll
        for (int j = 0; j < 8; j++) cpa16(d + CHUNK_B + j*16, gl + j*8);
        asm volatile("cp.async.commit_group;");
    }

    for (int c = 0; c < nch; c++) {
        if (c + 1 < nch) {
            uint32_t d = smbase + ((c+1)&1)*STAGE_B + dstoff;
            const __nv_bfloat16* gh = src + ((c+1)<<6);
            const __nv_bfloat16* gl = src + Ktot + ((c+1)<<6);
#pragma unroll
            for (int j = 0; j < 8; j++) cpa16(d + j*16, gh + j*8);
#pragma unroll
            for (int j = 0; j < 8; j++) cpa16(d + CHUNK_B + j*16, gl + j*8);
            asm volatile("cp.async.commit_group;");
            asm volatile("cp.async.wait_group 1;");
        } else {
            asm volatile("cp.async.wait_group 0;");
        }
        __syncthreads();

        const uint32_t stA = smbase + (c&1)*STAGE_B;
        const uint32_t stB = stA + 2*CHUNK_B;
#pragma unroll
        for (int ks = 0; ks < 4; ks++) {
            const uint32_t k0b = (uint32_t)ks*32u;
            uint32_t ah0[4], ah1[4], al0[4], al1[4], bh[4][4], bl[4][4];
            ldsm4(ah0, stA + aoff0 + k0b);
            ldsm4(ah1, stA + aoff1 + k0b);
            ldsm4(al0, stA + CHUNK_B + aoff0 + k0b);
            ldsm4(al1, stA + CHUNK_B + aoff1 + k0b);
#pragma unroll
            for (int p = 0; p < 4; p++) {
                ldsm4(bh[p], stB + boff0 + (uint32_t)p*(16*AS*2) + k0b);
                ldsm4(bl[p], stB + CHUNK_B + boff0 + (uint32_t)p*(16*AS*2) + k0b);
            }
#pragma unroll
            for (int nt = 0; nt < 8; nt++) {
                const int p = nt >> 1, i0 = (nt & 1) * 2;
                mma16816(acc[0][nt], ah0, bh[p][i0], bh[p][i0+1]);
                mma16816(acc[1][nt], ah1, bh[p][i0], bh[p][i0+1]);
                mma16816(acc[0][nt], ah0, bl[p][i0], bl[p][i0+1]);
                mma16816(acc[1][nt], ah1, bl[p][i0], bl[p][i0+1]);
                mma16816(acc[0][nt], al0, bh[p][i0], bh[p][i0+1]);
                mma16816(acc[1][nt], al1, bh[p][i0], bh[p][i0+1]);
            }
        }
        __syncthreads();
    }

    // epilogue: registers -> C (fp32)
    const int lq = lane >> 2, l4 = (lane & 3) << 1;
#pragma unroll
    for (int mt = 0; mt < 2; mt++) {
        int r = m0 + wm + mt*16 + lq;
        float* cp0 = C + (size_t)r*Ntot + n0 + wn + l4;
        float* cp1 = cp0 + (size_t)8*Ntot;
#pragma unroll
        for (int nt = 0; nt < 8; nt++) {
            *(float2*)(cp0 + nt*8) = make_float2(acc[mt][nt][0], acc[mt][nt][1]);
            *(float2*)(cp1 + nt*8) = make_float2(acc[mt][nt][2], acc[mt][nt][3]);
        }
    }
}

// ---------------- attention: one block per (head, window, batch) ------------
// writes output as bf16 hi|lo rows (consumed only by Wo GEMM)
__global__ __launch_bounds__(128) void attn_kernel(
    const float* __restrict__ kv, const float* __restrict__ qg,
    const float* __restrict__ bias, const float* __restrict__ mask,
    const int* __restrict__ kidx, __nv_bfloat16* __restrict__ obuf)
{
    __shared__ float qs[32*33];
    __shared__ float ks[128*33];
    __shared__ float sc[32*129];
    __shared__ float mv[128];
    const int t  = threadIdx.x;
    const int hd = blockIdx.x, w = blockIdx.y, b = blockIdx.z;
    const size_t kvbase = ((size_t)(b*NWw + w) * Hh) * 256 + hd*32;
    const size_t qbase  = ((size_t)(b*Nn + w*WQq)) * 256 + hd*32;

#pragma unroll
    for (int i = 0; i < 8; i++) {
        int s = t + i*128; int qq = s >> 5, d = s & 31;
        qs[qq*33 + d] = qg[qbase + (size_t)qq*256 + d];
    }
#pragma unroll
    for (int i = 0; i < 32; i++) {
        int s = t + i*128; int kk = s >> 5, d = s & 31;
        ks[kk*33 + d] = kv[kvbase + (size_t)kk*256 + d];
    }
    {
        int ki = kidx[w*Hh + t];
        mv[t] = (1.0f - mask[b*Nn + ki]) * -1e9f;
    }
    __syncthreads();

    const float* bptr = bias + ((((size_t)b*NWw + w)*NHh + hd)*WQq)*Hh + t;
    const float mvt = mv[t];
#pragma unroll 4
    for (int qq = 0; qq < 32; qq++) {
        float a = 0.f;
#pragma unroll
        for (int d = 0; d < 32; d++) a += qs[qq*33 + d]*ks[t*33 + d];
        sc[qq*129 + t] = a*0.17677669529663689f + bptr[(size_t)qq*Hh] + mvt;
    }
    __syncthreads();

#pragma unroll
    for (int i = 0; i < 32; i++) {
        int s = t + i*128; int kk = s >> 5, d = s & 31;
        ks[kk*33 + d] = kv[kvbase + (size_t)kk*256 + 128 + d];
    }
    {
        int qq = t >> 2, seg = t & 3;
        float* row = sc + qq*129 + seg*32;
        float mx = -1e30f;
#pragma unroll
        for (int j = 0; j < 32; j++) mx = fmaxf(mx, row[j]);
        mx = fmaxf(mx, __shfl_xor_sync(0xffffffffu, mx, 1));
        mx = fmaxf(mx, __shfl_xor_sync(0xffffffffu, mx, 2));
        float sum = 0.f;
#pragma unroll
        for (int j = 0; j < 32; j++) { float e = __expf(row[j]-mx); row[j] = e; sum += e; }
        sum += __shfl_xor_sync(0xffffffffu, sum, 1);
        sum += __shfl_xor_sync(0xffffffffu, sum, 2);
        float inv = 1.f/sum;
#pragma unroll
        for (int j = 0; j < 32; j++) row[j] *= inv;
    }
    __syncthreads();

    {
        int qq = t >> 2, ds = (t & 3) * 8;
        float acc[8];
#pragma unroll
        for (int j = 0; j < 8; j++) acc[j] = 0.f;
#pragma unroll 8
        for (int k = 0; k < 128; k++) {
            float s = sc[qq*129 + k];
#pragma unroll
            for (int j = 0; j < 8; j++) acc[j] += s*ks[k*33 + ds + j];
        }
        size_t nrow = (size_t)(b*Nn + w*WQq + qq);
        int col = hd*32 + ds;
        float v[8];
#pragma unroll
        for (int j = 0; j < 8; j++) {
            float g = qg[nrow*256 + 128 + col + j];
            v[j] = acc[j] * sigf(g);
        }
        uint32_t hi[4], lo[4];
#pragma unroll
        for (int j = 0; j < 4; j++) {
            __nv_bfloat162 h = __floats2bfloat162_rn(v[j*2], v[j*2+1]);
            float2 f = __bfloat1622float2(h);
            __nv_bfloat162 l = __floats2bfloat162_rn(v[j*2]-f.x, v[j*2+1]-f.y);
            hi[j] = *(uint32_t*)&h; lo[j] = *(uint32_t*)&l;
        }
        *(uint4*)(obuf + nrow*256 + col)       = make_uint4(hi[0],hi[1],hi[2],hi[3]);
        *(uint4*)(obuf + nrow*256 + 128 + col) = make_uint4(lo[0],lo[1],lo[2],lo[3]);
    }
}

// ---------------- elementwise / small kernels ----------------
__device__ __forceinline__ void store_hilo4(__nv_bfloat16* base, int off_lo,
                                            float a, float b, float c2, float d){
    __nv_bfloat162 h01 = __floats2bfloat162_rn(a, b);
    __nv_bfloat162 h23 = __floats2bfloat162_rn(c2, d);
    float2 f01 = __bfloat1622float2(h01);
    float2 f23 = __bfloat1622float2(h23);
    __nv_bfloat162 l01 = __floats2bfloat162_rn(a-f01.x, b-f01.y);
    __nv_bfloat162 l23 = __floats2bfloat162_rn(c2-f23.x, d-f23.y);
    *(uint2*)base = make_uint2(*(uint32_t*)&h01, *(uint32_t*)&h23);
    *(uint2*)(base + off_lo) = make_uint2(*(uint32_t*)&l01, *(uint32_t*)&l23);
}

// ln(c) -> bf16 hi|lo rows of 256
__global__ void ln_rows(const float* __restrict__ x, __nv_bfloat16* __restrict__ y) {
    int warp = threadIdx.x >> 5, lane = threadIdx.x & 31;
    size_t row = (size_t)blockIdx.x*8 + warp;
    float4 v = *(const float4*)(x + row*128 + lane*4);
    float s  = v.x+v.y+v.z+v.w;
    float ss = v.x*v.x+v.y*v.y+v.z*v.z+v.w*v.w;
#pragma unroll
    for (int o = 16; o; o >>= 1) { s += __shfl_xor_sync(~0u, s, o); ss += __shfl_xor_sync(~0u, ss, o); }
    float m = s*(1.f/128.f);
    float rstd = rsqrtf(ss*(1.f/128.f) - m*m + 1e-5f);
    store_hilo4(y + row*256 + lane*4, 128,
                (v.x-m)*rstd, (v.y-m)*rstd, (v.z-m)*rstd, (v.w-m)*rstd);
}

// h = ln(q) * sigmoid(X[:,0:128]) + X[:,128:256]; output bf16 hi|lo
__global__ void ew_hcur(const float* __restrict__ q, const float* __restrict__ X,
                        int xs, __nv_bfloat16* __restrict__ h) {
    int warp = threadIdx.x >> 5, lane = threadIdx.x & 31;
    size_t row = (size_t)blockIdx.x*8 + warp;
    float4 v = *(const float4*)(q + row*128 + lane*4);
    float s  = v.x+v.y+v.z+v.w;
    float ss = v.x*v.x+v.y*v.y+v.z*v.z+v.w*v.w;
#pragma unroll
    for (int o = 16; o; o >>= 1) { s += __shfl_xor_sync(~0u, s, o); ss += __shfl_xor_sync(~0u, ss, o); }
    float m = s*(1.f/128.f);
    float rstd = rsqrtf(ss*(1.f/128.f) - m*m + 1e-5f);
    float4 g  = *(const float4*)(X + row*xs + lane*4);
    float4 bb = *(const float4*)(X + row*xs + 128 + lane*4);
    store_hilo4(h + row*256 + lane*4, 128,
                (v.x-m)*rstd*sigf(g.x) + bb.x,
                (v.y-m)*rstd*sigf(g.y) + bb.y,
                (v.z-m)*rstd*sigf(g.z) + bb.z,
                (v.w-m)*rstd*sigf(g.w) + bb.w);
}

// q += sigmoid(gate) * x
__global__ void ew_resid(float* __restrict__ q, const float* __restrict__ gate,
                         int gs, const float* __restrict__ x) {
    size_t i4 = (size_t)blockIdx.x*blockDim.x + threadIdx.x;   // BN*32
    size_t row = i4 >> 5;
    int c4 = (int)(i4 & 31) << 2;
    float4 qq = *(float4*)(q + i4*4);
    float4 g  = *(const float4*)(gate + row*gs + c4);
    float4 xx = *(const float4*)(x + i4*4);
    qq.x += sigf(g.x)*xx.x; qq.y += sigf(g.y)*xx.y;
    qq.z += sigf(g.z)*xx.z; qq.w += sigf(g.w)*xx.w;
    *(float4*)(q + i4*4) = qq;
}

// glu: out[row, 256] bf16 hi|lo (row width 512 bf16)
__global__ void ew_glu(const float* __restrict__ T, __nv_bfloat16* __restrict__ out) {
    size_t i4 = (size_t)blockIdx.x*blockDim.x + threadIdx.x;   // BN*64
    size_t row = i4 >> 6;
    int c4 = (int)(i4 & 63) << 2;
    float4 a  = *(const float4*)(T + row*512 + c4);
    float4 bb = *(const float4*)(T + row*512 + 256 + c4);
    store_hilo4(out + row*512 + c4, 256,
                a.x*sigf(a.x)*bb.x, a.y*sigf(a.y)*bb.y,
                a.z*sigf(a.z)*bb.z, a.w*sigf(a.w)*bb.w);
}

// generic fp32 [M,K] -> bf16 hi|lo [M,2K]
__global__ void cvt_hilo(const float* __restrict__ in, __nv_bfloat16* __restrict__ out,
                         int K, int total4) {
    int i4 = blockIdx.x*blockDim.x + threadIdx.x;
    if (i4 >= total4) return;
    int kq = K >> 2;
    size_t row = i4 / kq;
    int k4 = (i4 % kq) << 2;
    float4 v = *(const float4*)(in + row*K + k4);
    store_hilo4(out + row*(2*K) + k4, K, v.x, v.y, v.z, v.w);
}

// one-shot transpose-pack of all weights into bf16 hi|lo layout
__global__ void pack_all(
    const float* __restrict__ Wcs,  const float* __restrict__ Wcb,
    const float* __restrict__ Wog,  const float* __restrict__ Wcs2,
    const float* __restrict__ Wcb2, const float* __restrict__ Wog2,
    const float* __restrict__ Wq,   const float* __restrict__ Wg,
    const float* __restrict__ Wk,   const float* __restrict__ Wv,
    const float* __restrict__ W1,   const float* __restrict__ W2,
    const float* __restrict__ Wo,   const float* __restrict__ W3,
    const float* __restrict__ a2q,  __nv_bfloat16* __restrict__ dst)
{
    const int total = Ll*PL2 + 49152;
    for (int i = blockIdx.x*blockDim.x + threadIdx.x; i < total; i += gridDim.x*blockDim.x) {
        float v; size_t bb; int n, k, Km;
        if (i >= Ll*PL2) {                       // a2q^T : [128 rows, K=384]
            int r = i - Ll*PL2;
            n = r / 384; k = r % 384; Km = 384;
            bb = (size_t)Ll*2*PL2;
            v = a2q[k*128 + n];
        } else {
            int l = i / PL2, o = i % PL2;
            size_t lb = (size_t)l*2*PL2;
            if (o < 98304) {                     // 6 square mats [128,128]
                int m = o >> 14, r = o & 16383;
                n = r >> 7; k = r & 127; Km = 128;
                bb = lb + (size_t)m*32768;
                const float* S = (m==0)?Wcs:(m==1)?Wcb:(m==2)?Wog:(m==3)?Wcs2:(m==4)?Wcb2:Wog2;
                v = S[l*16384 + k*128 + n];
            } else if (o < 131072) {             // [Wq|Wg] : [256,128]
                int r = o - 98304;
                n = r >> 7; k = r & 127; Km = 128;
                bb = lb + 196608;
                v = (n < 128) ? Wq[l*16384 + k*128 + n] : Wg[l*16384 + k*128 + n-128];
            } else if (o < 163840) {             // [Wk|Wv] : [256,128]
                int r = o - 131072;
                n = r >> 7; k = r & 127; Km = 128;
                bb = lb + 262144;
                v = (n < 128) ? Wk[l*16384 + k*128 + n] : Wv[l*16384 + k*128 + n-128];
            } else if (o < 229376) {             // [W1|W2]^T : [512,128]
                int r = o - 163840;
                n = r >> 7; k = r & 127; Km = 128;
                bb = lb + 327680;
                v = (n < 256) ? W1[l*32768 + k*256 + n] : W2[l*32768 + k*256 + n-256];
            } else if (o < 245760) {             // Wo^T : [128,128]
                int r = o - 229376;
                n = r >> 7; k = r & 127; Km = 128;
                bb = lb + 458752;
                v = Wo[l*16384 + k*128 + n];
            } else {                             // W3^T : [128,256]
                int r = o - 245760;
                n = r >> 8; k = r & 255; Km = 256;
                bb = lb + 491520;
                v = W3[l*32768 + k*128 + n];
            }
        }
        __nv_bfloat16 hi = __float2bfloat16(v);
        __nv_bfloat16 lo = __float2bfloat16(v - __bfloat162float(hi));
        dst[bb + (size_t)n*2*Km + k]      = hi;
        dst[bb + (size_t)n*2*Km + Km + k] = lo;
    }
}

__global__ void rowmap_kernel(const int* __restrict__ kidx, int* __restrict__ rm) {
    int i = blockIdx.x*256 + threadIdx.x;
    int b = i / (NWw*Hh);
    int r = i % (NWw*Hh);
    rm[i] = b*Nn + kidx[r];
}

__global__ void argmax_tok(const float* __restrict__ a2t, int* __restrict__ tok) {
    int warp = threadIdx.x >> 5, lane = threadIdx.x & 31;
    size_t row = (size_t)blockIdx.x*8 + warp;
    const float* p = a2t + row*Tt;
    float bv = -1e30f; int bi = 0;
    for (int j = lane; j < Tt; j += 32) { float v = p[j]; if (v > bv) { bv = v; bi = j; } }
#pragma unroll
    for (int o = 16; o; o >>= 1) {
        float ov = __shfl_xor_sync(~0u, bv, o);
        int   oi = __shfl_xor_sync(~0u, bi, o);
        if (ov > bv || (ov == bv && oi < bi)) { bv = ov; bi = oi; }
    }
    if (lane == 0) tok[row] = bi;
}

__global__ void addaw_kernel(const float* __restrict__ qin, const float* __restrict__ aw,
                             const int* __restrict__ tok, float* __restrict__ q) {
    size_t i4 = (size_t)blockIdx.x*256 + threadIdx.x;
    int row = (int)(i4 >> 5);
    int d4  = (int)(i4 & 31) << 2;
    int b = row >> 14;
    int t = tok[row];
    float4 v = *(const float4*)(qin + ((size_t)row << 7) + d4);
    float4 w = *(const float4*)(aw + (((size_t)b*Tt + t) << 7) + d4);
    v.x += w.x; v.y += w.y; v.z += w.z; v.w += w.w;
    *(float4*)(q + ((size_t)row << 7) + d4) = v;
}

__global__ void sfeat_kernel(const float* __restrict__ q, const float* __restrict__ mask,
                             const int* __restrict__ tok, float* __restrict__ sf) {
    size_t e = (size_t)blockIdx.x*256 + threadIdx.x;
    int row = (int)(e >> 7);
    int d = (int)(e & 127);
    int b = row >> 14;
    int t = tok[row];
    atomicAdd(&sf[(((size_t)b*Tt + t) << 7) + d], q[e]*mask[row]);
}

__global__ __launch_bounds__(128) void restype_kernel(
    const float* __restrict__ sf, const float* __restrict__ Wres,
    const float* __restrict__ bres, float* __restrict__ out) {
    __shared__ float sr[128];
    int t = threadIdx.x;
    size_t row = blockIdx.x;
    sr[t] = sf[row*128 + t];
    __syncthreads();
    if (t < NTOKk) {
        float acc = bres[t];
#pragma unroll 16
        for (int d = 0; d < 128; d++) acc += sr[d]*Wres[d*NTOKk + t];
        out[row*NTOKk + t] = acc;
    }
}

__global__ __launch_bounds__(128) void rupdate_kernel(
    const float* __restrict__ q, const float* __restrict__ g,
    const float* __restrict__ bb, const float* __restrict__ Wpos,
    float* __restrict__ out) {
    __shared__ float r1[128], r2[128];
    __shared__ float ms, rs;
    int d = threadIdx.x;
    size_t row = blockIdx.x;
    float x = q[row*128 + d];
    r1[d] = x; r2[d] = x*x;
    __syncthreads();
    for (int o = 64; o; o >>= 1) { if (d < o) { r1[d] += r1[d+o]; r2[d] += r2[d+o]; } __syncthreads(); }
    if (d == 0) {
        float m = r1[0]*(1.f/128.f);
        float v = r2[0]*(1.f/128.f) - m*m;
        ms = m; rs = rsqrtf(v + 1e-5f);
    }
    __syncthreads();
    float y = (x - ms)*rs*g[d] + bb[d];
    float p0 = y*Wpos[d*3], p1 = y*Wpos[d*3+1], p2 = y*Wpos[d*3+2];
    r1[d] = p0; r2[d] = p1;
    __syncthreads();
    for (int o = 64; o; o >>= 1) { if (d < o) { r1[d] += r1[d+o]; r2[d] += r2[d+o]; } __syncthreads(); }
    if (d == 0) { out[row*3] = r1[0]; out[row*3+1] = r2[0]; }
    __syncthreads();
    r1[d] = p2;
    __syncthreads();
    for (int o = 64; o; o >>= 1) { if (d < o) { r1[d] += r1[d+o]; } __syncthreads(); }
    if (d == 0) out[row*3+2] = r1[0];
}

// ---------------- host launcher ----------------
extern "C" void kernel_launch(void* const* d_in, const int* in_sizes, int n_in,
                              void* d_out, int out_size) {
    (void)in_sizes; (void)n_in; (void)out_size;
    const float* a    = (const float*)d_in[0];
    const float* qin  = (const float*)d_in[1];
    const float* c    = (const float*)d_in[2];
    const float* bias = (const float*)d_in[3];
    const float* a2t  = (const float*)d_in[4];
    const float* mask = (const float*)d_in[5];
    const int*   kidx = (const int*)  d_in[6];
    const float* a2q  = (const float*)d_in[7];
    const float* Wq   = (const float*)d_in[8];
    const float* Wk   = (const float*)d_in[9];
    const float* Wv   = (const float*)d_in[10];
    const float* Wg   = (const float*)d_in[11];
    const float* Wo   = (const float*)d_in[12];
    const float* Wcs  = (const float*)d_in[13];
    const float* Wcb  = (const float*)d_in[14];
    const float* Wog  = (const float*)d_in[15];
    const float* Wcs2 = (const float*)d_in[16];
    const float* Wcb2 = (const float*)d_in[17];
    const float* Wog2 = (const float*)d_in[18];
    const float* W1   = (const float*)d_in[19];
    const float* W2   = (const float*)d_in[20];
    const float* W3   = (const float*)d_in[21];
    const float* ln_g = (const float*)d_in[22];
    const float* ln_b = (const float*)d_in[23];
    const float* Wpos = (const float*)d_in[24];
    const float* Wres = (const float*)d_in[25];
    const float* bres = (const float*)d_in[26];
    float* out = (float*)d_out;

    float *pq, *pt1, *pt2, *pkv, *pcng, *paw, *psf;
    __nv_bfloat16 *pcn, *ph, *pt3, *pwp;
    int *ptok, *prm;
    cudaGetSymbolAddress((void**)&pq,   g_q);
    cudaGetSymbolAddress((void**)&pcn,  g_cn);
    cudaGetSymbolAddress((void**)&ph,   g_h);
    cudaGetSymbolAddress((void**)&pt1,  g_t1);
    cudaGetSymbolAddress((void**)&pt2,  g_t2);
    cudaGetSymbolAddress((void**)&pt3,  g_t3);
    cudaGetSymbolAddress((void**)&pkv,  g_kv);
    cudaGetSymbolAddress((void**)&pcng, g_cng);
    cudaGetSymbolAddress((void**)&paw,  g_aw);
    cudaGetSymbolAddress((void**)&psf,  g_sf);
    cudaGetSymbolAddress((void**)&pwp,  g_wp);
    cudaGetSymbolAddress((void**)&ptok, g_tok);
    cudaGetSymbolAddress((void**)&prm,  g_rm);

    cudaFuncSetAttribute(gemm_tc, cudaFuncAttributeMaxDynamicSharedMemorySize, GEMM_SMEM);

    // bf16 views of fp32 scratch for chained GEMM operands
    __nv_bfloat16* acvt  = (__nv_bfloat16*)pcng;          // prologue only
    __nv_bfloat16* pglu  = (__nv_bfloat16*)pt1;           // glu out (rows of 512 bf16)

    // prologue
    pack_all<<<512, 256>>>(Wcs, Wcb, Wog, Wcs2, Wcb2, Wog2, Wq, Wg, Wk, Wv,
                           W1, W2, Wo, W3, a2q, pwp);
    rowmap_kernel<<<BKV/256, 256>>>(kidx, prm);
    argmax_tok<<<BN/8, 256>>>(a2t, ptok);
    cvt_hilo<<<(Bb*Tt*Ss/4 + 255)/256, 256>>>(a, acvt, Ss, Bb*Tt*Ss/4);
    gemm_tc<<<dim3(1, (Bb*Tt)/128), 256, GEMM_SMEM>>>(acvt, pwp + (size_t)Ll*2*PL2, paw, 128, Ss, nullptr);
    addaw_kernel<<<(BN*32)/256, 256>>>(qin, paw, ptok, pq);
    ln_rows<<<BN/8, 256>>>(c, pcn);

    for (int l = 0; l < Ll; l++) {
        __nv_bfloat16* wl = pwp + (size_t)l*2*PL2;
        // all six cn projections: [cs|cb|og|cs2|cb2|og2]
        gemm_tc<<<dim3(6, BN/128), 256, GEMM_SMEM>>>(pcn, wl, pcng, 768, Dd, nullptr);
        // hcur = ln(q)*sig(cs) + cb  -> bf16 hi|lo
        ew_hcur<<<BN/8, 256>>>(pq, pcng, 768, ph);
        // Q|G projection (fp32 out, consumed by attention)
        gemm_tc<<<dim3(2, BN/128), 256, GEMM_SMEM>>>(ph, wl + 196608, pt2, 256, Dd, nullptr);
        // gathered K|V projection
        gemm_tc<<<dim3(2, BKV/128), 256, GEMM_SMEM>>>(ph, wl + 262144, pkv, 256, Dd, prm);
        // attention (+ sigmoid(Wg) gate) -> bf16 hi|lo
        attn_kernel<<<dim3(NHh, NWw, Bb), 128>>>(pkv, pt2, bias, mask, kidx, pt3);
        // q += sig(og) * (o@Wo)
        gemm_tc<<<dim3(1, BN/128), 256, GEMM_SMEM>>>(pt3, wl + 458752, pt1, 128, Dd, nullptr);
        ew_resid<<<(BN*32)/256, 256>>>(pq, pcng + 256, 768, pt1);
        // h2 = ln(q)*sig(cs2) + cb2 -> bf16 hi|lo
        ew_hcur<<<BN/8, 256>>>(pq, pcng + 384, 768, ph);
        // FFN
        gemm_tc<<<dim3(4, BN/128), 256, GEMM_SMEM>>>(ph, wl + 327680, pkv, 512, Dd, nullptr);
        ew_glu<<<(BN*64)/256, 256>>>(pkv, pglu);
        gemm_tc<<<dim3(1, BN/128), 256, GEMM_SMEM>>>(pglu, wl + 491520, pt2, 128, 256, nullptr);
        ew_resid<<<(BN*32)/256, 256>>>(pq, pcng + 640, 768, pt2);
    }

    // epilogue
    cudaMemsetAsync(psf, 0, (size_t)Bb*Tt*Dd*sizeof(float));
    sfeat_kernel<<<(BN*128)/256, 256>>>(pq, mask, ptok, psf);
    restype_kernel<<<Bb*Tt, 128>>>(psf, Wres, bres, out + (size_t)BN*3);
    rupdate_kernel<<<BN, 128>>>(pq, ln_g, ln_b, Wpos, out);
}

// round 6
// speedup vs baseline: 1.4940x; 1.0070x over previous
#include <cuda_runtime.h>
#include <cuda_bf16.h>
#include <cstdint>

#define Bb   2
#define Nn   16384
#define Tt   2048
#define Dd   128
#define Ss   384
#define NWw  512
#define WQq  32
#define Hh   128
#define Ll   3
#define NHh  4
#define NTOKk 33
#define BN   (Bb*Nn)          // 32768
#define PL2  278528           // packed weight floats per layer (bf16 = 2x)

// ---------------- scratch (device globals; allocation-free) ----------------
__device__ __align__(256) float g_q   [BN*Dd];
__device__ __align__(256) __nv_bfloat16 g_cn [BN*256];     // ln(c) hi|lo
__device__ __align__(256) __nv_bfloat16 g_h  [BN*256];     // hcur hi|lo
__device__ __align__(256) __nv_bfloat16 g_t3 [BN*256];     // attn out hi|lo
__device__ __align__(256) float g_t1  [BN*256];
__device__ __align__(256) float g_t2  [(size_t)BN*512];    // Q|G|K|V
__device__ __align__(256) float g_kv  [(size_t)BN*512];    // FFN intermediate
__device__ __align__(256) float g_cng [(size_t)BN*768];    // cn gates; also a_cvt
__device__ __align__(256) float g_aw  [Bb*Tt*Dd];
__device__ __align__(256) float g_sf  [Bb*Tt*Dd];
__device__ __align__(256) __nv_bfloat16 g_wp [2*(Ll*PL2 + 49152)];
__device__ int g_tok[BN];

__device__ __forceinline__ float sigf(float x){ return 1.f/(1.f + __expf(-x)); }

__device__ __forceinline__ uint32_t s2u(const void* p){
    uint32_t a;
    asm("{ .reg .u64 t; cvta.to.shared.u64 t, %1; cvt.u32.u64 %0, t; }" : "=r"(a) : "l"(p));
    return a;
}

// ---------------- bf16 mma.sync GEMM, tile 256x128, warp 64x64 -------------
// A[M,2K] bf16 hi|lo rows, Bt[N,2K] bf16 hi|lo rows, C[M,N] fp32.
// D = Ah@Bh + Ah@Bl + Al@Bh, fp32 register accumulate.
// K-chunk 64, 2-stage cp.async pipeline. Smem stage layout (bytes):
//   [0)      A-hi 256x72 bf16  (36864)
//   [36864)  A-lo               (36864)
//   [73728)  B-hi 128x72 bf16  (18432)
//   [92160)  B-lo               (18432)
#define AS       72
#define STAGE_B  110592
#define GEMM_SMEM (2*STAGE_B)       // 221184

__device__ __forceinline__ void mma16816(float* d, const uint32_t* a,
                                         uint32_t b0, uint32_t b1){
    asm volatile(
        "mma.sync.aligned.m16n8k16.row.col.f32.bf16.bf16.f32 "
        "{%0,%1,%2,%3}, {%4,%5,%6,%7}, {%8,%9}, {%0,%1,%2,%3};"
        : "+f"(d[0]), "+f"(d[1]), "+f"(d[2]), "+f"(d[3])
        : "r"(a[0]), "r"(a[1]), "r"(a[2]), "r"(a[3]), "r"(b0), "r"(b1));
}
__device__ __forceinline__ void ldsm4(uint32_t* r, uint32_t a){
    asm volatile("ldmatrix.sync.aligned.m8n8.x4.shared.b16 {%0,%1,%2,%3}, [%4];"
        : "=r"(r[0]), "=r"(r[1]), "=r"(r[2]), "=r"(r[3]) : "r"(a));
}
__device__ __forceinline__ void cpa16(uint32_t d, const void* s){
    asm volatile("cp.async.cg.shared.global [%0], [%1], 16;" :: "r"(d), "l"(s));
}
__device__ __forceinline__ void gemm_load_chunk(
    const __nv_bfloat16* const* srcs, const uint32_t* doffs, uint32_t st, int c){
#pragma unroll
    for (int j = 0; j < 3; j++) {
        const __nv_bfloat16* s = srcs[j] + (c << 6);
        uint32_t d = st + doffs[j];
#pragma unroll
        for (int i = 0; i < 8; i++) cpa16(d + i*16, s + i*8);
    }
    asm volatile("cp.async.commit_group;");
}

__global__ __launch_bounds__(256) void gemm_tc(
    const __nv_bfloat16* __restrict__ A, const __nv_bfloat16* __restrict__ Bt,
    float* __restrict__ C, int Ntot, int Ktot)
{
    extern __shared__ __nv_bfloat16 smb[];
    const uint32_t smbase = s2u(smb);
    const int tid = threadIdx.x, wid = tid >> 5, lane = tid & 31;
    const int m0 = blockIdx.y << 8, n0 = blockIdx.x << 7;

    // loader assignment: 768 row-buffers of 128B, 3 per thread
    const __nv_bfloat16* srcs[3];
    uint32_t doffs[3];
    srcs[0] = A + (size_t)(m0 + tid)*(2*Ktot);
    doffs[0] = (uint32_t)tid*144u;
    srcs[1] = srcs[0] + Ktot;
    doffs[1] = 36864u + (uint32_t)tid*144u;
    if (tid < 128) {
        srcs[2] = Bt + (size_t)(n0 + tid)*(2*Ktot);
        doffs[2] = 73728u + (uint32_t)tid*144u;
    } else {
        srcs[2] = Bt + (size_t)(n0 + tid - 128)*(2*Ktot) + Ktot;
        doffs[2] = 92160u + (uint32_t)(tid - 128)*144u;
    }

    const int wm = (wid & 3) << 6;     // 0,64,128,192
    const int wn = (wid >> 2) << 6;    // 0,64
    const uint32_t aoff0 =
        ((uint32_t)(wm + ((lane>>3)&1)*8 + (lane&7))*AS + (uint32_t)(lane>>4)*8)*2u;
    const uint32_t boff0 = 73728u +
        ((uint32_t)(wn + (lane>>4)*8 + (lane&7))*AS + (uint32_t)((lane>>3)&1)*8)*2u;

    float acc[4][8][4];
#pragma unroll
    for (int a = 0; a < 4; a++)
#pragma unroll
        for (int b = 0; b < 8; b++)
#pragma unroll
            for (int k = 0; k < 4; k++) acc[a][b][k] = 0.f;

    const int nch = Ktot >> 6;
    gemm_load_chunk(srcs, doffs, smbase, 0);

    for (int c = 0; c < nch; c++) {
        if (c + 1 < nch) {
            gemm_load_chunk(srcs, doffs, smbase + ((c+1)&1)*STAGE_B, c+1);
            asm volatile("cp.async.wait_group 1;");
        } else {
            asm volatile("cp.async.wait_group 0;");
        }
        __syncthreads();
        const uint32_t st = smbase + (uint32_t)(c&1)*STAGE_B;
#pragma unroll
        for (int ks = 0; ks < 4; ks++) {
            const uint32_t k0b = (uint32_t)ks*32u;
            uint32_t ah[4][4], al[4][4];
#pragma unroll
            for (int mt = 0; mt < 4; mt++) {
                ldsm4(ah[mt], st + aoff0 + (uint32_t)mt*2304u + k0b);
                ldsm4(al[mt], st + aoff0 + 36864u + (uint32_t)mt*2304u + k0b);
            }
#pragma unroll
            for (int p = 0; p < 4; p++) {
                uint32_t bh[4], bl[4];
                ldsm4(bh, st + boff0 + (uint32_t)p*2304u + k0b);
                ldsm4(bl, st + boff0 + 18432u + (uint32_t)p*2304u + k0b);
#pragma unroll
                for (int mt = 0; mt < 4; mt++) {
#pragma unroll
                    for (int i = 0; i < 2; i++) {
                        float* d = acc[mt][p*2 + i];
                        mma16816(d, ah[mt], bh[i*2], bh[i*2+1]);
                        mma16816(d, ah[mt], bl[i*2], bl[i*2+1]);
                        mma16816(d, al[mt], bh[i*2], bh[i*2+1]);
                    }
                }
            }
        }
        __syncthreads();
    }

    // epilogue
    const int lq = lane >> 2, l4 = (lane & 3) << 1;
#pragma unroll
    for (int mt = 0; mt < 4; mt++) {
        int r = m0 + wm + mt*16 + lq;
        float* cp0 = C + (size_t)r*Ntot + n0 + wn + l4;
        float* cp1 = cp0 + (size_t)8*Ntot;
#pragma unroll
        for (int nt = 0; nt < 8; nt++) {
            *(float2*)(cp0 + nt*8) = make_float2(acc[mt][nt][0], acc[mt][nt][1]);
            *(float2*)(cp1 + nt*8) = make_float2(acc[mt][nt][2], acc[mt][nt][3]);
        }
    }
}

// ---------------- attention: one block per (head, window, batch) ------------
// qg: (BN, 512) fp32 = [Q | G | K | V]; K/V rows gathered via kidx.
__global__ __launch_bounds__(128) void attn_kernel(
    const float* __restrict__ qg, const float* __restrict__ bias,
    const float* __restrict__ mask, const int* __restrict__ kidx,
    __nv_bfloat16* __restrict__ obuf)
{
    __shared__ float qs[32*33];
    __shared__ float ks[128*33];
    __shared__ float sc[32*129];
    __shared__ float mv[128];
    __shared__ int   kid[128];
    const int t  = threadIdx.x;
    const int hd = blockIdx.x, w = blockIdx.y, b = blockIdx.z;
    const size_t qbase = ((size_t)(b*Nn + w*WQq))*512 + hd*32;

#pragma unroll
    for (int i = 0; i < 8; i++) {
        int s = t + i*128; int qq = s >> 5, d = s & 31;
        qs[qq*33 + d] = qg[qbase + (size_t)qq*512 + d];
    }
    {
        int ki = kidx[w*Hh + t];
        kid[t] = b*Nn + ki;
        mv[t] = (1.0f - mask[b*Nn + ki]) * -1e9f;
    }
    __syncthreads();

    // gathered K (col 256)
#pragma unroll
    for (int i = 0; i < 32; i++) {
        int s = t + i*128; int kk = s >> 5, d = s & 31;
        ks[kk*33 + d] = qg[(size_t)kid[kk]*512 + 256 + hd*32 + d];
    }
    __syncthreads();

    const float* bptr = bias + ((((size_t)b*NWw + w)*NHh + hd)*WQq)*Hh + t;
    const float mvt = mv[t];
#pragma unroll 4
    for (int qq = 0; qq < 32; qq++) {
        float a = 0.f;
#pragma unroll
        for (int d = 0; d < 32; d++) a += qs[qq*33 + d]*ks[t*33 + d];
        sc[qq*129 + t] = a*0.17677669529663689f + bptr[(size_t)qq*Hh] + mvt;
    }
    __syncthreads();

    // gathered V (col 384) while softmax runs on sc
#pragma unroll
    for (int i = 0; i < 32; i++) {
        int s = t + i*128; int kk = s >> 5, d = s & 31;
        ks[kk*33 + d] = qg[(size_t)kid[kk]*512 + 384 + hd*32 + d];
    }
    {
        int qq = t >> 2, seg = t & 3;
        float* row = sc + qq*129 + seg*32;
        float mx = -1e30f;
#pragma unroll
        for (int j = 0; j < 32; j++) mx = fmaxf(mx, row[j]);
        mx = fmaxf(mx, __shfl_xor_sync(0xffffffffu, mx, 1));
        mx = fmaxf(mx, __shfl_xor_sync(0xffffffffu, mx, 2));
        float sum = 0.f;
#pragma unroll
        for (int j = 0; j < 32; j++) { float e = __expf(row[j]-mx); row[j] = e; sum += e; }
        sum += __shfl_xor_sync(0xffffffffu, sum, 1);
        sum += __shfl_xor_sync(0xffffffffu, sum, 2);
        float inv = 1.f/sum;
#pragma unroll
        for (int j = 0; j < 32; j++) row[j] *= inv;
    }
    __syncthreads();

    {
        int qq = t >> 2, ds = (t & 3) * 8;
        float acc[8];
#pragma unroll
        for (int j = 0; j < 8; j++) acc[j] = 0.f;
#pragma unroll 8
        for (int k = 0; k < 128; k++) {
            float s = sc[qq*129 + k];
#pragma unroll
            for (int j = 0; j < 8; j++) acc[j] += s*ks[k*33 + ds + j];
        }
        size_t nrow = (size_t)(b*Nn + w*WQq + qq);
        int col = hd*32 + ds;
        float v[8];
#pragma unroll
        for (int j = 0; j < 8; j++) {
            float g = qg[nrow*512 + 128 + col + j];
            v[j] = acc[j] * sigf(g);
        }
        uint32_t hi[4], lo[4];
#pragma unroll
        for (int j = 0; j < 4; j++) {
            __nv_bfloat162 h = __floats2bfloat162_rn(v[j*2], v[j*2+1]);
            float2 f = __bfloat1622float2(h);
            __nv_bfloat162 l = __floats2bfloat162_rn(v[j*2]-f.x, v[j*2+1]-f.y);
            hi[j] = *(uint32_t*)&h; lo[j] = *(uint32_t*)&l;
        }
        *(uint4*)(obuf + nrow*256 + col)       = make_uint4(hi[0],hi[1],hi[2],hi[3]);
        *(uint4*)(obuf + nrow*256 + 128 + col) = make_uint4(lo[0],lo[1],lo[2],lo[3]);
    }
}

// ---------------- elementwise / small kernels ----------------
__device__ __forceinline__ void store_hilo4(__nv_bfloat16* base, int off_lo,
                                            float a, float b, float c2, float d){
    __nv_bfloat162 h01 = __floats2bfloat162_rn(a, b);
    __nv_bfloat162 h23 = __floats2bfloat162_rn(c2, d);
    float2 f01 = __bfloat1622float2(h01);
    float2 f23 = __bfloat1622float2(h23);
    __nv_bfloat162 l01 = __floats2bfloat162_rn(a-f01.x, b-f01.y);
    __nv_bfloat162 l23 = __floats2bfloat162_rn(c2-f23.x, d-f23.y);
    *(uint2*)base = make_uint2(*(uint32_t*)&h01, *(uint32_t*)&h23);
    *(uint2*)(base + off_lo) = make_uint2(*(uint32_t*)&l01, *(uint32_t*)&l23);
}

__global__ void ln_rows(const float* __restrict__ x, __nv_bfloat16* __restrict__ y) {
    int warp = threadIdx.x >> 5, lane = threadIdx.x & 31;
    size_t row = (size_t)blockIdx.x*8 + warp;
    float4 v = *(const float4*)(x + row*128 + lane*4);
    float s  = v.x+v.y+v.z+v.w;
    float ss = v.x*v.x+v.y*v.y+v.z*v.z+v.w*v.w;
#pragma unroll
    for (int o = 16; o; o >>= 1) { s += __shfl_xor_sync(~0u, s, o); ss += __shfl_xor_sync(~0u, ss, o); }
    float m = s*(1.f/128.f);
    float rstd = rsqrtf(ss*(1.f/128.f) - m*m + 1e-5f);
    store_hilo4(y + row*256 + lane*4, 128,
                (v.x-m)*rstd, (v.y-m)*rstd, (v.z-m)*rstd, (v.w-m)*rstd);
}

__global__ void ew_hcur(const float* __restrict__ q, const float* __restrict__ X,
                        int xs, __nv_bfloat16* __restrict__ h) {
    int warp = threadIdx.x >> 5, lane = threadIdx.x & 31;
    size_t row = (size_t)blockIdx.x*8 + warp;
    float4 v = *(const float4*)(q + row*128 + lane*4);
    float s  = v.x+v.y+v.z+v.w;
    float ss = v.x*v.x+v.y*v.y+v.z*v.z+v.w*v.w;
#pragma unroll
    for (int o = 16; o; o >>= 1) { s += __shfl_xor_sync(~0u, s, o); ss += __shfl_xor_sync(~0u, ss, o); }
    float m = s*(1.f/128.f);
    float rstd = rsqrtf(ss*(1.f/128.f) - m*m + 1e-5f);
    float4 g  = *(const float4*)(X + row*xs + lane*4);
    float4 bb = *(const float4*)(X + row*xs + 128 + lane*4);
    store_hilo4(h + row*256 + lane*4, 128,
                (v.x-m)*rstd*sigf(g.x) + bb.x,
                (v.y-m)*rstd*sigf(g.y) + bb.y,
                (v.z-m)*rstd*sigf(g.z) + bb.z,
                (v.w-m)*rstd*sigf(g.w) + bb.w);
}

__global__ void ew_resid(float* __restrict__ q, const float* __restrict__ gate,
                         int gs, const float* __restrict__ x) {
    size_t i4 = (size_t)blockIdx.x*blockDim.x + threadIdx.x;   // BN*32
    size_t row = i4 >> 5;
    int c4 = (int)(i4 & 31) << 2;
    float4 qq = *(float4*)(q + i4*4);
    float4 g  = *(const float4*)(gate + row*gs + c4);
    float4 xx = *(const float4*)(x + i4*4);
    qq.x += sigf(g.x)*xx.x; qq.y += sigf(g.y)*xx.y;
    qq.z += sigf(g.z)*xx.z; qq.w += sigf(g.w)*xx.w;
    *(float4*)(q + i4*4) = qq;
}

__global__ void ew_glu(const float* __restrict__ T, __nv_bfloat16* __restrict__ out) {
    size_t i4 = (size_t)blockIdx.x*blockDim.x + threadIdx.x;   // BN*64
    size_t row = i4 >> 6;
    int c4 = (int)(i4 & 63) << 2;
    float4 a  = *(const float4*)(T + row*512 + c4);
    float4 bb = *(const float4*)(T + row*512 + 256 + c4);
    store_hilo4(out + row*512 + c4, 256,
                a.x*sigf(a.x)*bb.x, a.y*sigf(a.y)*bb.y,
                a.z*sigf(a.z)*bb.z, a.w*sigf(a.w)*bb.w);
}

__global__ void cvt_hilo(const float* __restrict__ in, __nv_bfloat16* __restrict__ out,
                         int K, int total4) {
    int i4 = blockIdx.x*blockDim.x + threadIdx.x;
    if (i4 >= total4) return;
    int kq = K >> 2;
    size_t row = i4 / kq;
    int k4 = (i4 % kq) << 2;
    float4 v = *(const float4*)(in + row*K + k4);
    store_hilo4(out + row*(2*K) + k4, K, v.x, v.y, v.z, v.w);
}

__global__ void pack_all(
    const float* __restrict__ Wcs,  const float* __restrict__ Wcb,
    const float* __restrict__ Wog,  const float* __restrict__ Wcs2,
    const float* __restrict__ Wcb2, const float* __restrict__ Wog2,
    const float* __restrict__ Wq,   const float* __restrict__ Wg,
    const float* __restrict__ Wk,   const float* __restrict__ Wv,
    const float* __restrict__ W1,   const float* __restrict__ W2,
    const float* __restrict__ Wo,   const float* __restrict__ W3,
    const float* __restrict__ a2q,  __nv_bfloat16* __restrict__ dst)
{
    const int total = Ll*PL2 + 49152;
    for (int i = blockIdx.x*blockDim.x + threadIdx.x; i < total; i += gridDim.x*blockDim.x) {
        float v; size_t bb; int n, k, Km;
        if (i >= Ll*PL2) {                       // a2q^T : [128 rows, K=384]
            int r = i - Ll*PL2;
            n = r / 384; k = r % 384; Km = 384;
            bb = (size_t)Ll*2*PL2;
            v = a2q[k*128 + n];
        } else {
            int l = i / PL2, o = i % PL2;
            size_t lb = (size_t)l*2*PL2;
            if (o < 98304) {                     // 6 square mats [128,128]
                int m = o >> 14, r = o & 16383;
                n = r >> 7; k = r & 127; Km = 128;
                bb = lb + (size_t)m*32768;
                const float* S = (m==0)?Wcs:(m==1)?Wcb:(m==2)?Wog:(m==3)?Wcs2:(m==4)?Wcb2:Wog2;
                v = S[l*16384 + k*128 + n];
            } else if (o < 131072) {             // [Wq|Wg] : [256,128]
                int r = o - 98304;
                n = r >> 7; k = r & 127; Km = 128;
                bb = lb + 196608;
                v = (n < 128) ? Wq[l*16384 + k*128 + n] : Wg[l*16384 + k*128 + n-128];
            } else if (o < 163840) {             // [Wk|Wv] : [256,128] (contiguous after QG -> QGKV N=512)
                int r = o - 131072;
                n = r >> 7; k = r & 127; Km = 128;
                bb = lb + 262144;
                v = (n < 128) ? Wk[l*16384 + k*128 + n] : Wv[l*16384 + k*128 + n-128];
            } else if (o < 229376) {             // [W1|W2]^T : [512,128]
                int r = o - 163840;
                n = r >> 7; k = r & 127; Km = 128;
                bb = lb + 327680;
                v = (n < 256) ? W1[l*32768 + k*256 + n] : W2[l*32768 + k*256 + n-256];
            } else if (o < 245760) {             // Wo^T : [128,128]
                int r = o - 229376;
                n = r >> 7; k = r & 127; Km = 128;
                bb = lb + 458752;
                v = Wo[l*16384 + k*128 + n];
            } else {                             // W3^T : [128,256]
                int r = o - 245760;
                n = r >> 8; k = r & 255; Km = 256;
                bb = lb + 491520;
                v = W3[l*32768 + k*128 + n];
            }
        }
        __nv_bfloat16 hi = __float2bfloat16(v);
        __nv_bfloat16 lo = __float2bfloat16(v - __bfloat162float(hi));
        dst[bb + (size_t)n*2*Km + k]      = hi;
        dst[bb + (size_t)n*2*Km + Km + k] = lo;
    }
}

__global__ void argmax_tok(const float* __restrict__ a2t, int* __restrict__ tok) {
    int warp = threadIdx.x >> 5, lane = threadIdx.x & 31;
    size_t row = (size_t)blockIdx.x*8 + warp;
    const float* p = a2t + row*Tt;
    float bv = -1e30f; int bi = 0;
    for (int j = lane; j < Tt; j += 32) { float v = p[j]; if (v > bv) { bv = v; bi = j; } }
#pragma unroll
    for (int o = 16; o; o >>= 1) {
        float ov = __shfl_xor_sync(~0u, bv, o);
        int   oi = __shfl_xor_sync(~0u, bi, o);
        if (ov > bv || (ov == bv && oi < bi)) { bv = ov; bi = oi; }
    }
    if (lane == 0) tok[row] = bi;
}

__global__ void addaw_kernel(const float* __restrict__ qin, const float* __restrict__ aw,
                             const int* __restrict__ tok, float* __restrict__ q) {
    size_t i4 = (size_t)blockIdx.x*256 + threadIdx.x;
    int row = (int)(i4 >> 5);
    int d4  = (int)(i4 & 31) << 2;
    int b = row >> 14;
    int t = tok[row];
    float4 v = *(const float4*)(qin + ((size_t)row << 7) + d4);
    float4 w = *(const float4*)(aw + (((size_t)b*Tt + t) << 7) + d4);
    v.x += w.x; v.y += w.y; v.z += w.z; v.w += w.w;
    *(float4*)(q + ((size_t)row << 7) + d4) = v;
}

__global__ void sfeat_kernel(const float* __restrict__ q, const float* __restrict__ mask,
                             const int* __restrict__ tok, float* __restrict__ sf) {
    size_t e = (size_t)blockIdx.x*256 + threadIdx.x;
    int row = (int)(e >> 7);
    int d = (int)(e & 127);
    int b = row >> 14;
    int t = tok[row];
    atomicAdd(&sf[(((size_t)b*Tt + t) << 7) + d], q[e]*mask[row]);
}

__global__ __launch_bounds__(128) void restype_kernel(
    const float* __restrict__ sf, const float* __restrict__ Wres,
    const float* __restrict__ bres, float* __restrict__ out) {
    __shared__ float sr[128];
    int t = threadIdx.x;
    size_t row = blockIdx.x;
    sr[t] = sf[row*128 + t];
    __syncthreads();
    if (t < NTOKk) {
        float acc = bres[t];
#pragma unroll 16
        for (int d = 0; d < 128; d++) acc += sr[d]*Wres[d*NTOKk + t];
        out[row*NTOKk + t] = acc;
    }
}

__global__ __launch_bounds__(128) void rupdate_kernel(
    const float* __restrict__ q, const float* __restrict__ g,
    const float* __restrict__ bb, const float* __restrict__ Wpos,
    float* __restrict__ out) {
    __shared__ float r1[128], r2[128];
    __shared__ float ms, rs;
    int d = threadIdx.x;
    size_t row = blockIdx.x;
    float x = q[row*128 + d];
    r1[d] = x; r2[d] = x*x;
    __syncthreads();
    for (int o = 64; o; o >>= 1) { if (d < o) { r1[d] += r1[d+o]; r2[d] += r2[d+o]; } __syncthreads(); }
    if (d == 0) {
        float m = r1[0]*(1.f/128.f);
        float v = r2[0]*(1.f/128.f) - m*m;
        ms = m; rs = rsqrtf(v + 1e-5f);
    }
    __syncthreads();
    float y = (x - ms)*rs*g[d] + bb[d];
    float p0 = y*Wpos[d*3], p1 = y*Wpos[d*3+1], p2 = y*Wpos[d*3+2];
    r1[d] = p0; r2[d] = p1;
    __syncthreads();
    for (int o = 64; o; o >>= 1) { if (d < o) { r1[d] += r1[d+o]; r2[d] += r2[d+o]; } __syncthreads(); }
    if (d == 0) { out[row*3] = r1[0]; out[row*3+1] = r2[0]; }
    __syncthreads();
    r1[d] = p2;
    __syncthreads();
    for (int o = 64; o; o >>= 1) { if (d < o) { r1[d] += r1[d+o]; } __syncthreads(); }
    if (d == 0) out[row*3+2] = r1[0];
}

// ---------------- host launcher ----------------
extern "C" void kernel_launch(void* const* d_in, const int* in_sizes, int n_in,
                              void* d_out, int out_size) {
    (void)in_sizes; (void)n_in; (void)out_size;
    const float* a    = (const float*)d_in[0];
    const float* qin  = (const float*)d_in[1];
    const float* c    = (const float*)d_in[2];
    const float* bias = (const float*)d_in[3];
    const float* a2t  = (const float*)d_in[4];
    const float* mask = (const float*)d_in[5];
    const int*   kidx = (const int*)  d_in[6];
    const float* a2q  = (const float*)d_in[7];
    const float* Wq   = (const float*)d_in[8];
    const float* Wk   = (const float*)d_in[9];
    const float* Wv   = (const float*)d_in[10];
    const float* Wg   = (const float*)d_in[11];
    const float* Wo   = (const float*)d_in[12];
    const float* Wcs  = (const float*)d_in[13];
    const float* Wcb  = (const float*)d_in[14];
    const float* Wog  = (const float*)d_in[15];
    const float* Wcs2 = (const float*)d_in[16];
    const float* Wcb2 = (const float*)d_in[17];
    const float* Wog2 = (const float*)d_in[18];
    const float* W1   = (const float*)d_in[19];
    const float* W2   = (const float*)d_in[20];
    const float* W3   = (const float*)d_in[21];
    const float* ln_g = (const float*)d_in[22];
    const float* ln_b = (const float*)d_in[23];
    const float* Wpos = (const float*)d_in[24];
    const float* Wres = (const float*)d_in[25];
    const float* bres = (const float*)d_in[26];
    float* out = (float*)d_out;

    float *pq, *pt1, *pt2, *pkv, *pcng, *paw, *psf;
    __nv_bfloat16 *pcn, *ph, *pt3, *pwp;
    int *ptok;
    cudaGetSymbolAddress((void**)&pq,   g_q);
    cudaGetSymbolAddress((void**)&pcn,  g_cn);
    cudaGetSymbolAddress((void**)&ph,   g_h);
    cudaGetSymbolAddress((void**)&pt1,  g_t1);
    cudaGetSymbolAddress((void**)&pt2,  g_t2);
    cudaGetSymbolAddress((void**)&pt3,  g_t3);
    cudaGetSymbolAddress((void**)&pkv,  g_kv);
    cudaGetSymbolAddress((void**)&pcng, g_cng);
    cudaGetSymbolAddress((void**)&paw,  g_aw);
    cudaGetSymbolAddress((void**)&psf,  g_sf);
    cudaGetSymbolAddress((void**)&pwp,  g_wp);
    cudaGetSymbolAddress((void**)&ptok, g_tok);

    cudaFuncSetAttribute(gemm_tc, cudaFuncAttributeMaxDynamicSharedMemorySize, GEMM_SMEM);

    __nv_bfloat16* acvt = (__nv_bfloat16*)pcng;   // prologue-only bf16 view
    __nv_bfloat16* pglu = (__nv_bfloat16*)pt1;    // glu out (rows of 512 bf16)

    // prologue
    pack_all<<<512, 256>>>(Wcs, Wcb, Wog, Wcs2, Wcb2, Wog2, Wq, Wg, Wk, Wv,
                           W1, W2, Wo, W3, a2q, pwp);
    argmax_tok<<<BN/8, 256>>>(a2t, ptok);
    cvt_hilo<<<(Bb*Tt*Ss/4 + 255)/256, 256>>>(a, acvt, Ss, Bb*Tt*Ss/4);
    gemm_tc<<<dim3(1, (Bb*Tt)/256), 256, GEMM_SMEM>>>(acvt, pwp + (size_t)Ll*2*PL2, paw, 128, Ss);
    addaw_kernel<<<(BN*32)/256, 256>>>(qin, paw, ptok, pq);
    ln_rows<<<BN/8, 256>>>(c, pcn);

    for (int l = 0; l < Ll; l++) {
        __nv_bfloat16* wl = pwp + (size_t)l*2*PL2;
        // all six cn projections: [cs|cb|og|cs2|cb2|og2]
        gemm_tc<<<dim3(6, BN/256), 256, GEMM_SMEM>>>(pcn, wl, pcng, 768, Dd);
        // hcur = ln(q)*sig(cs) + cb  -> bf16 hi|lo
        ew_hcur<<<BN/8, 256>>>(pq, pcng, 768, ph);
        // fused Q|G|K|V projection on unique rows
        gemm_tc<<<dim3(4, BN/256), 256, GEMM_SMEM>>>(ph, wl + 196608, pt2, 512, Dd);
        // attention: gathers K/V via kidx, applies sigmoid(G) gate -> bf16 hi|lo
        attn_kernel<<<dim3(NHh, NWw, Bb), 128>>>(pt2, bias, mask, kidx, pt3);
        // q += sig(og) * (o@Wo)
        gemm_tc<<<dim3(1, BN/256), 256, GEMM_SMEM>>>(pt3, wl + 458752, pt1, 128, Dd);
        ew_resid<<<(BN*32)/256, 256>>>(pq, pcng + 256, 768, pt1);
        // h2 = ln(q)*sig(cs2) + cb2 -> bf16 hi|lo
        ew_hcur<<<BN/8, 256>>>(pq, pcng + 384, 768, ph);
        // FFN
        gemm_tc<<<dim3(4, BN/256), 256, GEMM_SMEM>>>(ph, wl + 327680, pkv, 512, Dd);
        ew_glu<<<(BN*64)/256, 256>>>(pkv, pglu);
        gemm_tc<<<dim3(1, BN/256), 256, GEMM_SMEM>>>(pglu, wl + 491520, pt2, 128, 256);
        ew_resid<<<(BN*32)/256, 256>>>(pq, pcng + 640, 768, pt2);
    }

    // epilogue
    cudaMemsetAsync(psf, 0, (size_t)Bb*Tt*Dd*sizeof(float));
    sfeat_kernel<<<(BN*128)/256, 256>>>(pq, mask, ptok, psf);
    restype_kernel<<<Bb*Tt, 128>>>(psf, Wres, bres, out + (size_t)BN*3);
    rupdate_kernel<<<BN, 128>>>(pq, ln_g, ln_b, Wpos, out);
}

// round 7
// speedup vs baseline: 1.5173x; 1.0156x over previous
#include <cuda_runtime.h>
#include <cuda_bf16.h>
#include <cstdint>

#define Bb   2
#define Nn   16384
#define Tt   2048
#define Dd   128
#define Ss   384
#define NWw  512
#define WQq  32
#define Hh   128
#define Ll   3
#define NHh  4
#define NTOKk 33
#define BN   (Bb*Nn)          // 32768
#define PL2  278528           // packed weight floats per layer (bf16 = 2x)

// ---------------- scratch (device globals; allocation-free) ----------------
__device__ __align__(256) float g_q   [BN*Dd];
__device__ __align__(256) __nv_bfloat16 g_cn [BN*256];     // ln(c) hi|lo
__device__ __align__(256) __nv_bfloat16 g_h  [BN*256];     // hcur hi|lo
__device__ __align__(256) __nv_bfloat16 g_t3 [BN*256];     // attn out hi|lo
__device__ __align__(256) float g_t1  [BN*256];
__device__ __align__(256) float g_t2  [(size_t)BN*512];    // Q|G|K|V
__device__ __align__(256) float g_kv  [(size_t)BN*512];    // FFN intermediate
__device__ __align__(256) float g_cng [(size_t)BN*768];    // cn gates; also a_cvt
__device__ __align__(256) float g_aw  [Bb*Tt*Dd];
__device__ __align__(256) float g_sf  [Bb*Tt*Dd];
__device__ __align__(256) __nv_bfloat16 g_wp [2*(Ll*PL2 + 49152)];
__device__ int g_tok[BN];

__device__ __forceinline__ float sigf(float x){ return 1.f/(1.f + __expf(-x)); }

__device__ __forceinline__ uint32_t s2u(const void* p){
    uint32_t a;
    asm("{ .reg .u64 t; cvta.to.shared.u64 t, %1; cvt.u32.u64 %0, t; }" : "=r"(a) : "l"(p));
    return a;
}

// ---------------- bf16 mma.sync GEMM, tile 128x128, warp 32x64 -------------
// A[M,2K] bf16 hi|lo rows, Bt[N,2K] bf16 hi|lo rows, C[M,N] fp32.
// D = Ah@Bh + Ah@Bl + Al@Bh, fp32 register accumulate.
// K-chunk 32, 2-stage cp.async pipeline, 80KB smem -> 2 CTAs/SM.
// Stage layout (bytes): Ah@0, Al@10240, Bh@20480, Bl@30720 (stride 40 bf16)
#define AS2   40
#define BUFB  (128*AS2*2)      // 10240
#define STG   (4*BUFB)         // 40960
#define GEMM_SMEM (2*STG)      // 81920

__device__ __forceinline__ void mma16816(float* d, const uint32_t* a,
                                         uint32_t b0, uint32_t b1){
    asm volatile(
        "mma.sync.aligned.m16n8k16.row.col.f32.bf16.bf16.f32 "
        "{%0,%1,%2,%3}, {%4,%5,%6,%7}, {%8,%9}, {%0,%1,%2,%3};"
        : "+f"(d[0]), "+f"(d[1]), "+f"(d[2]), "+f"(d[3])
        : "r"(a[0]), "r"(a[1]), "r"(a[2]), "r"(a[3]), "r"(b0), "r"(b1));
}
__device__ __forceinline__ void ldsm4(uint32_t* r, uint32_t a){
    asm volatile("ldmatrix.sync.aligned.m8n8.x4.shared.b16 {%0,%1,%2,%3}, [%4];"
        : "=r"(r[0]), "=r"(r[1]), "=r"(r[2]), "=r"(r[3]) : "r"(a));
}
__device__ __forceinline__ void cpa16(uint32_t d, const void* s){
    asm volatile("cp.async.cg.shared.global [%0], [%1], 16;" :: "r"(d), "l"(s));
}

__global__ __launch_bounds__(256, 2) void gemm_tc(
    const __nv_bfloat16* __restrict__ A, const __nv_bfloat16* __restrict__ Bt,
    float* __restrict__ C, int Ntot, int Ktot)
{
    extern __shared__ __nv_bfloat16 smb[];
    const uint32_t smbase = s2u(smb);
    const int tid = threadIdx.x, wid = tid >> 5, lane = tid & 31;
    const int m0 = blockIdx.y << 7, n0 = blockIdx.x << 7;

    // loaders: thread t -> 32 bf16 (64B) of one A row and one B row per chunk
    const int lr = tid & 127;
    const int isLo = tid >> 7;                 // 0: hi-half threads, 1: lo-half
    const __nv_bfloat16* srcA = A + (size_t)(m0 + lr)*(2*Ktot) + (isLo ? Ktot : 0);
    const __nv_bfloat16* srcB = Bt + (size_t)(n0 + lr)*(2*Ktot) + (isLo ? Ktot : 0);
    const uint32_t dA = (uint32_t)(isLo*BUFB + lr*(AS2*2));
    const uint32_t dB = (uint32_t)(2*BUFB + isLo*BUFB + lr*(AS2*2));

    const int wm = (wid & 3) << 5;     // 0,32,64,96
    const int wn = (wid >> 2) << 6;    // 0,64
    const uint32_t aoff =
        ((uint32_t)(wm + ((lane>>3)&1)*8 + (lane&7))*AS2 + (uint32_t)(lane>>4)*8)*2u;
    const uint32_t boff = 2u*BUFB +
        ((uint32_t)(wn + (lane>>4)*8 + (lane&7))*AS2 + (uint32_t)((lane>>3)&1)*8)*2u;

    float acc[2][8][4];
#pragma unroll
    for (int a = 0; a < 2; a++)
#pragma unroll
        for (int b = 0; b < 8; b++)
#pragma unroll
            for (int k = 0; k < 4; k++) acc[a][b][k] = 0.f;

    const int nch = Ktot >> 5;

    // issue chunk 0
    {
        uint32_t st = smbase;
#pragma unroll
        for (int i = 0; i < 4; i++) cpa16(st + dA + i*16, srcA + i*8);
#pragma unroll
        for (int i = 0; i < 4; i++) cpa16(st + dB + i*16, srcB + i*8);
        asm volatile("cp.async.commit_group;");
    }

    for (int c = 0; c < nch; c++) {
        if (c + 1 < nch) {
            uint32_t st = smbase + ((c+1)&1)*STG;
            const __nv_bfloat16* sa = srcA + ((c+1)<<5);
            const __nv_bfloat16* sb = srcB + ((c+1)<<5);
#pragma unroll
            for (int i = 0; i < 4; i++) cpa16(st + dA + i*16, sa + i*8);
#pragma unroll
            for (int i = 0; i < 4; i++) cpa16(st + dB + i*16, sb + i*8);
            asm volatile("cp.async.commit_group;");
            asm volatile("cp.async.wait_group 1;");
        } else {
            asm volatile("cp.async.wait_group 0;");
        }
        __syncthreads();
        const uint32_t st = smbase + (uint32_t)(c&1)*STG;
#pragma unroll
        for (int ks = 0; ks < 2; ks++) {
            const uint32_t k0b = (uint32_t)ks*32u;
            uint32_t ah[2][4], al[2][4];
            ldsm4(ah[0], st + aoff + k0b);
            ldsm4(ah[1], st + aoff + 1280u + k0b);
            ldsm4(al[0], st + BUFB + aoff + k0b);
            ldsm4(al[1], st + BUFB + aoff + 1280u + k0b);
#pragma unroll
            for (int p = 0; p < 4; p++) {
                uint32_t bh[4], bl[4];
                ldsm4(bh, st + boff + (uint32_t)p*1280u + k0b);
                ldsm4(bl, st + boff + BUFB + (uint32_t)p*1280u + k0b);
#pragma unroll
                for (int i = 0; i < 2; i++) {
                    float* d0 = acc[0][p*2 + i];
                    float* d1 = acc[1][p*2 + i];
                    mma16816(d0, ah[0], bh[i*2], bh[i*2+1]);
                    mma16816(d1, ah[1], bh[i*2], bh[i*2+1]);
                    mma16816(d0, ah[0], bl[i*2], bl[i*2+1]);
                    mma16816(d1, ah[1], bl[i*2], bl[i*2+1]);
                    mma16816(d0, al[0], bh[i*2], bh[i*2+1]);
                    mma16816(d1, al[1], bh[i*2], bh[i*2+1]);
                }
            }
        }
        __syncthreads();
    }

    // epilogue
    const int lq = lane >> 2, l4 = (lane & 3) << 1;
#pragma unroll
    for (int mt = 0; mt < 2; mt++) {
        int r = m0 + wm + mt*16 + lq;
        float* cp0 = C + (size_t)r*Ntot + n0 + wn + l4;
        float* cp1 = cp0 + (size_t)8*Ntot;
#pragma unroll
        for (int nt = 0; nt < 8; nt++) {
            *(float2*)(cp0 + nt*8) = make_float2(acc[mt][nt][0], acc[mt][nt][1]);
            *(float2*)(cp1 + nt*8) = make_float2(acc[mt][nt][2], acc[mt][nt][3]);
        }
    }
}

// ---------------- attention: one block per (head, window, batch) ------------
// qg: (BN, 512) fp32 = [Q | G | K | V]; K/V rows gathered via kidx.
__global__ __launch_bounds__(128) void attn_kernel(
    const float* __restrict__ qg, const float* __restrict__ bias,
    const float* __restrict__ mask, const int* __restrict__ kidx,
    __nv_bfloat16* __restrict__ obuf)
{
    __shared__ float qs[32*33];
    __shared__ float ks[128*33];
    __shared__ float sc[32*129];
    __shared__ float mv[128];
    __shared__ int   kid[128];
    const int t  = threadIdx.x;
    const int hd = blockIdx.x, w = blockIdx.y, b = blockIdx.z;
    const size_t qbase = ((size_t)(b*Nn + w*WQq))*512 + hd*32;

#pragma unroll
    for (int i = 0; i < 8; i++) {
        int s = t + i*128; int qq = s >> 5, d = s & 31;
        qs[qq*33 + d] = qg[qbase + (size_t)qq*512 + d];
    }
    {
        int ki = kidx[w*Hh + t];
        kid[t] = b*Nn + ki;
        mv[t] = (1.0f - mask[b*Nn + ki]) * -1e9f;
    }
    __syncthreads();

    // gathered K (col 256)
#pragma unroll
    for (int i = 0; i < 32; i++) {
        int s = t + i*128; int kk = s >> 5, d = s & 31;
        ks[kk*33 + d] = qg[(size_t)kid[kk]*512 + 256 + hd*32 + d];
    }
    __syncthreads();

    const float* bptr = bias + ((((size_t)b*NWw + w)*NHh + hd)*WQq)*Hh + t;
    const float mvt = mv[t];
#pragma unroll 4
    for (int qq = 0; qq < 32; qq++) {
        float a = 0.f;
#pragma unroll
        for (int d = 0; d < 32; d++) a += qs[qq*33 + d]*ks[t*33 + d];
        sc[qq*129 + t] = a*0.17677669529663689f + bptr[(size_t)qq*Hh] + mvt;
    }
    __syncthreads();

    // gathered V (col 384) while softmax runs on sc
#pragma unroll
    for (int i = 0; i < 32; i++) {
        int s = t + i*128; int kk = s >> 5, d = s & 31;
        ks[kk*33 + d] = qg[(size_t)kid[kk]*512 + 384 + hd*32 + d];
    }
    {
        int qq = t >> 2, seg = t & 3;
        float* row = sc + qq*129 + seg*32;
        float mx = -1e30f;
#pragma unroll
        for (int j = 0; j < 32; j++) mx = fmaxf(mx, row[j]);
        mx = fmaxf(mx, __shfl_xor_sync(0xffffffffu, mx, 1));
        mx = fmaxf(mx, __shfl_xor_sync(0xffffffffu, mx, 2));
        float sum = 0.f;
#pragma unroll
        for (int j = 0; j < 32; j++) { float e = __expf(row[j]-mx); row[j] = e; sum += e; }
        sum += __shfl_xor_sync(0xffffffffu, sum, 1);
        sum += __shfl_xor_sync(0xffffffffu, sum, 2);
        float inv = 1.f/sum;
#pragma unroll
        for (int j = 0; j < 32; j++) row[j] *= inv;
    }
    __syncthreads();

    {
        int qq = t >> 2, ds = (t & 3) * 8;
        float acc[8];
#pragma unroll
        for (int j = 0; j < 8; j++) acc[j] = 0.f;
#pragma unroll 8
        for (int k = 0; k < 128; k++) {
            float s = sc[qq*129 + k];
#pragma unroll
            for (int j = 0; j < 8; j++) acc[j] += s*ks[k*33 + ds + j];
        }
        size_t nrow = (size_t)(b*Nn + w*WQq + qq);
        int col = hd*32 + ds;
        float v[8];
#pragma unroll
        for (int j = 0; j < 8; j++) {
            float g = qg[nrow*512 + 128 + col + j];
            v[j] = acc[j] * sigf(g);
        }
        uint32_t hi[4], lo[4];
#pragma unroll
        for (int j = 0; j < 4; j++) {
            __nv_bfloat162 h = __floats2bfloat162_rn(v[j*2], v[j*2+1]);
            float2 f = __bfloat1622float2(h);
            __nv_bfloat162 l = __floats2bfloat162_rn(v[j*2]-f.x, v[j*2+1]-f.y);
            hi[j] = *(uint32_t*)&h; lo[j] = *(uint32_t*)&l;
        }
        *(uint4*)(obuf + nrow*256 + col)       = make_uint4(hi[0],hi[1],hi[2],hi[3]);
        *(uint4*)(obuf + nrow*256 + 128 + col) = make_uint4(lo[0],lo[1],lo[2],lo[3]);
    }
}

// ---------------- elementwise / small kernels ----------------
__device__ __forceinline__ void store_hilo4(__nv_bfloat16* base, int off_lo,
                                            float a, float b, float c2, float d){
    __nv_bfloat162 h01 = __floats2bfloat162_rn(a, b);
    __nv_bfloat162 h23 = __floats2bfloat162_rn(c2, d);
    float2 f01 = __bfloat1622float2(h01);
    float2 f23 = __bfloat1622float2(h23);
    __nv_bfloat162 l01 = __floats2bfloat162_rn(a-f01.x, b-f01.y);
    __nv_bfloat162 l23 = __floats2bfloat162_rn(c2-f23.x, d-f23.y);
    *(uint2*)base = make_uint2(*(uint32_t*)&h01, *(uint32_t*)&h23);
    *(uint2*)(base + off_lo) = make_uint2(*(uint32_t*)&l01, *(uint32_t*)&l23);
}

__global__ void ln_rows(const float* __restrict__ x, __nv_bfloat16* __restrict__ y) {
    int warp = threadIdx.x >> 5, lane = threadIdx.x & 31;
    size_t row = (size_t)blockIdx.x*8 + warp;
    float4 v = *(const float4*)(x + row*128 + lane*4);
    float s  = v.x+v.y+v.z+v.w;
    float ss = v.x*v.x+v.y*v.y+v.z*v.z+v.w*v.w;
#pragma unroll
    for (int o = 16; o; o >>= 1) { s += __shfl_xor_sync(~0u, s, o); ss += __shfl_xor_sync(~0u, ss, o); }
    float m = s*(1.f/128.f);
    float rstd = rsqrtf(ss*(1.f/128.f) - m*m + 1e-5f);
    store_hilo4(y + row*256 + lane*4, 128,
                (v.x-m)*rstd, (v.y-m)*rstd, (v.z-m)*rstd, (v.w-m)*rstd);
}

__global__ void ew_hcur(const float* __restrict__ q, const float* __restrict__ X,
                        int xs, __nv_bfloat16* __restrict__ h) {
    int warp = threadIdx.x >> 5, lane = threadIdx.x & 31;
    size_t row = (size_t)blockIdx.x*8 + warp;
    float4 v = *(const float4*)(q + row*128 + lane*4);
    float s  = v.x+v.y+v.z+v.w;
    float ss = v.x*v.x+v.y*v.y+v.z*v.z+v.w*v.w;
#pragma unroll
    for (int o = 16; o; o >>= 1) { s += __shfl_xor_sync(~0u, s, o); ss += __shfl_xor_sync(~0u, ss, o); }
    float m = s*(1.f/128.f);
    float rstd = rsqrtf(ss*(1.f/128.f) - m*m + 1e-5f);
    float4 g  = *(const float4*)(X + row*xs + lane*4);
    float4 bb = *(const float4*)(X + row*xs + 128 + lane*4);
    store_hilo4(h + row*256 + lane*4, 128,
                (v.x-m)*rstd*sigf(g.x) + bb.x,
                (v.y-m)*rstd*sigf(g.y) + bb.y,
                (v.z-m)*rstd*sigf(g.z) + bb.z,
                (v.w-m)*rstd*sigf(g.w) + bb.w);
}

__global__ void ew_resid(float* __restrict__ q, const float* __restrict__ gate,
                         int gs, const float* __restrict__ x) {
    size_t i4 = (size_t)blockIdx.x*blockDim.x + threadIdx.x;   // BN*32
    size_t row = i4 >> 5;
    int c4 = (int)(i4 & 31) << 2;
    float4 qq = *(float4*)(q + i4*4);
    float4 g  = *(const float4*)(gate + row*gs + c4);
    float4 xx = *(const float4*)(x + i4*4);
    qq.x += sigf(g.x)*xx.x; qq.y += sigf(g.y)*xx.y;
    qq.z += sigf(g.z)*xx.z; qq.w += sigf(g.w)*xx.w;
    *(float4*)(q + i4*4) = qq;
}

__global__ void ew_glu(const float* __restrict__ T, __nv_bfloat16* __restrict__ out) {
    size_t i4 = (size_t)blockIdx.x*blockDim.x + threadIdx.x;   // BN*64
    size_t row = i4 >> 6;
    int c4 = (int)(i4 & 63) << 2;
    float4 a  = *(const float4*)(T + row*512 + c4);
    float4 bb = *(const float4*)(T + row*512 + 256 + c4);
    store_hilo4(out + row*512 + c4, 256,
                a.x*sigf(a.x)*bb.x, a.y*sigf(a.y)*bb.y,
                a.z*sigf(a.z)*bb.z, a.w*sigf(a.w)*bb.w);
}

__global__ void cvt_hilo(const float* __restrict__ in, __nv_bfloat16* __restrict__ out,
                         int K, int total4) {
    int i4 = blockIdx.x*blockDim.x + threadIdx.x;
    if (i4 >= total4) return;
    int kq = K >> 2;
    size_t row = i4 / kq;
    int k4 = (i4 % kq) << 2;
    float4 v = *(const float4*)(in + row*K + k4);
    store_hilo4(out + row*(2*K) + k4, K, v.x, v.y, v.z, v.w);
}

__global__ void pack_all(
    const float* __restrict__ Wcs,  const float* __restrict__ Wcb,
    const float* __restrict__ Wog,  const float* __restrict__ Wcs2,
    const float* __restrict__ Wcb2, const float* __restrict__ Wog2,
    const float* __restrict__ Wq,   const float* __restrict__ Wg,
    const float* __restrict__ Wk,   const float* __restrict__ Wv,
    const float* __restrict__ W1,   const float* __restrict__ W2,
    const float* __restrict__ Wo,   const float* __restrict__ W3,
    const float* __restrict__ a2q,  __nv_bfloat16* __restrict__ dst)
{
    const int total = Ll*PL2 + 49152;
    for (int i = blockIdx.x*blockDim.x + threadIdx.x; i < total; i += gridDim.x*blockDim.x) {
        float v; size_t bb; int n, k, Km;
        if (i >= Ll*PL2) {                       // a2q^T : [128 rows, K=384]
            int r = i - Ll*PL2;
            n = r / 384; k = r % 384; Km = 384;
            bb = (size_t)Ll*2*PL2;
            v = a2q[k*128 + n];
        } else {
            int l = i / PL2, o = i % PL2;
            size_t lb = (size_t)l*2*PL2;
            if (o < 98304) {                     // 6 square mats [128,128]
                int m = o >> 14, r = o & 16383;
                n = r >> 7; k = r & 127; Km = 128;
                bb = lb + (size_t)m*32768;
                const float* S = (m==0)?Wcs:(m==1)?Wcb:(m==2)?Wog:(m==3)?Wcs2:(m==4)?Wcb2:Wog2;
                v = S[l*16384 + k*128 + n];
            } else if (o < 131072) {             // [Wq|Wg] : [256,128]
                int r = o - 98304;
                n = r >> 7; k = r & 127; Km = 128;
                bb = lb + 196608;
                v = (n < 128) ? Wq[l*16384 + k*128 + n] : Wg[l*16384 + k*128 + n-128];
            } else if (o < 163840) {             // [Wk|Wv] : [256,128]
                int r = o - 131072;
                n = r >> 7; k = r & 127; Km = 128;
                bb = lb + 262144;
                v = (n < 128) ? Wk[l*16384 + k*128 + n] : Wv[l*16384 + k*128 + n-128];
            } else if (o < 229376) {             // [W1|W2]^T : [512,128]
                int r = o - 163840;
                n = r >> 7; k = r & 127; Km = 128;
                bb = lb + 327680;
                v = (n < 256) ? W1[l*32768 + k*256 + n] : W2[l*32768 + k*256 + n-256];
            } else if (o < 245760) {             // Wo^T : [128,128]
                int r = o - 229376;
                n = r >> 7; k = r & 127; Km = 128;
                bb = lb + 458752;
                v = Wo[l*16384 + k*128 + n];
            } else {                             // W3^T : [128,256]
                int r = o - 245760;
                n = r >> 8; k = r & 255; Km = 256;
                bb = lb + 491520;
                v = W3[l*32768 + k*128 + n];
            }
        }
        __nv_bfloat16 hi = __float2bfloat16(v);
        __nv_bfloat16 lo = __float2bfloat16(v - __bfloat162float(hi));
        dst[bb + (size_t)n*2*Km + k]      = hi;
        dst[bb + (size_t)n*2*Km + Km + k] = lo;
    }
}

__global__ void argmax_tok(const float* __restrict__ a2t, int* __restrict__ tok) {
    int warp = threadIdx.x >> 5, lane = threadIdx.x & 31;
    size_t row = (size_t)blockIdx.x*8 + warp;
    const float* p = a2t + row*Tt;
    float bv = -1e30f; int bi = 0;
    for (int j = lane; j < Tt; j += 32) { float v = p[j]; if (v > bv) { bv = v; bi = j; } }
#pragma unroll
    for (int o = 16; o; o >>= 1) {
        float ov = __shfl_xor_sync(~0u, bv, o);
        int   oi = __shfl_xor_sync(~0u, bi, o);
        if (ov > bv || (ov == bv && oi < bi)) { bv = ov; bi = oi; }
    }
    if (lane == 0) tok[row] = bi;
}

__global__ void addaw_kernel(const float* __restrict__ qin, const float* __restrict__ aw,
                             const int* __restrict__ tok, float* __restrict__ q) {
    size_t i4 = (size_t)blockIdx.x*256 + threadIdx.x;
    int row = (int)(i4 >> 5);
    int d4  = (int)(i4 & 31) << 2;
    int b = row >> 14;
    int t = tok[row];
    float4 v = *(const float4*)(qin + ((size_t)row << 7) + d4);
    float4 w = *(const float4*)(aw + (((size_t)b*Tt + t) << 7) + d4);
    v.x += w.x; v.y += w.y; v.z += w.z; v.w += w.w;
    *(float4*)(q + ((size_t)row << 7) + d4) = v;
}

__global__ void sfeat_kernel(const float* __restrict__ q, const float* __restrict__ mask,
                             const int* __restrict__ tok, float* __restrict__ sf) {
    size_t e = (size_t)blockIdx.x*256 + threadIdx.x;
    int row = (int)(e >> 7);
    int d = (int)(e & 127);
    int b = row >> 14;
    int t = tok[row];
    atomicAdd(&sf[(((size_t)b*Tt + t) << 7) + d], q[e]*mask[row]);
}

__global__ __launch_bounds__(128) void restype_kernel(
    const float* __restrict__ sf, const float* __restrict__ Wres,
    const float* __restrict__ bres, float* __restrict__ out) {
    __shared__ float sr[128];
    int t = threadIdx.x;
    size_t row = blockIdx.x;
    sr[t] = sf[row*128 + t];
    __syncthreads();
    if (t < NTOKk) {
        float acc = bres[t];
#pragma unroll 16
        for (int d = 0; d < 128; d++) acc += sr[d]*Wres[d*NTOKk + t];
        out[row*NTOKk + t] = acc;
    }
}

__global__ __launch_bounds__(128) void rupdate_kernel(
    const float* __restrict__ q, const float* __restrict__ g,
    const float* __restrict__ bb, const float* __restrict__ Wpos,
    float* __restrict__ out) {
    __shared__ float r1[128], r2[128];
    __shared__ float ms, rs;
    int d = threadIdx.x;
    size_t row = blockIdx.x;
    float x = q[row*128 + d];
    r1[d] = x; r2[d] = x*x;
    __syncthreads();
    for (int o = 64; o; o >>= 1) { if (d < o) { r1[d] += r1[d+o]; r2[d] += r2[d+o]; } __syncthreads(); }
    if (d == 0) {
        float m = r1[0]*(1.f/128.f);
        float v = r2[0]*(1.f/128.f) - m*m;
        ms = m; rs = rsqrtf(v + 1e-5f);
    }
    __syncthreads();
    float y = (x - ms)*rs*g[d] + bb[d];
    float p0 = y*Wpos[d*3], p1 = y*Wpos[d*3+1], p2 = y*Wpos[d*3+2];
    r1[d] = p0; r2[d] = p1;
    __syncthreads();
    for (int o = 64; o; o >>= 1) { if (d < o) { r1[d] += r1[d+o]; r2[d] += r2[d+o]; } __syncthreads(); }
    if (d == 0) { out[row*3] = r1[0]; out[row*3+1] = r2[0]; }
    __syncthreads();
    r1[d] = p2;
    __syncthreads();
    for (int o = 64; o; o >>= 1) { if (d < o) { r1[d] += r1[d+o]; } __syncthreads(); }
    if (d == 0) out[row*3+2] = r1[0];
}

// ---------------- host launcher ----------------
extern "C" void kernel_launch(void* const* d_in, const int* in_sizes, int n_in,
                              void* d_out, int out_size) {
    (void)in_sizes; (void)n_in; (void)out_size;
    const float* a    = (const float*)d_in[0];
    const float* qin  = (const float*)d_in[1];
    const float* c    = (const float*)d_in[2];
    const float* bias = (const float*)d_in[3];
    const float* a2t  = (const float*)d_in[4];
    const float* mask = (const float*)d_in[5];
    const int*   kidx = (const int*)  d_in[6];
    const float* a2q  = (const float*)d_in[7];
    const float* Wq   = (const float*)d_in[8];
    const float* Wk   = (const float*)d_in[9];
    const float* Wv   = (const float*)d_in[10];
    const float* Wg   = (const float*)d_in[11];
    const float* Wo   = (const float*)d_in[12];
    const float* Wcs  = (const float*)d_in[13];
    const float* Wcb  = (const float*)d_in[14];
    const float* Wog  = (const float*)d_in[15];
    const float* Wcs2 = (const float*)d_in[16];
    const float* Wcb2 = (const float*)d_in[17];
    const float* Wog2 = (const float*)d_in[18];
    const float* W1   = (const float*)d_in[19];
    const float* W2   = (const float*)d_in[20];
    const float* W3   = (const float*)d_in[21];
    const float* ln_g = (const float*)d_in[22];
    const float* ln_b = (const float*)d_in[23];
    const float* Wpos = (const float*)d_in[24];
    const float* Wres = (const float*)d_in[25];
    const float* bres = (const float*)d_in[26];
    float* out = (float*)d_out;

    float *pq, *pt1, *pt2, *pkv, *pcng, *paw, *psf;
    __nv_bfloat16 *pcn, *ph, *pt3, *pwp;
    int *ptok;
    cudaGetSymbolAddress((void**)&pq,   g_q);
    cudaGetSymbolAddress((void**)&pcn,  g_cn);
    cudaGetSymbolAddress((void**)&ph,   g_h);
    cudaGetSymbolAddress((void**)&pt1,  g_t1);
    cudaGetSymbolAddress((void**)&pt2,  g_t2);
    cudaGetSymbolAddress((void**)&pt3,  g_t3);
    cudaGetSymbolAddress((void**)&pkv,  g_kv);
    cudaGetSymbolAddress((void**)&pcng, g_cng);
    cudaGetSymbolAddress((void**)&paw,  g_aw);
    cudaGetSymbolAddress((void**)&psf,  g_sf);
    cudaGetSymbolAddress((void**)&pwp,  g_wp);
    cudaGetSymbolAddress((void**)&ptok, g_tok);

    cudaFuncSetAttribute(gemm_tc, cudaFuncAttributeMaxDynamicSharedMemorySize, GEMM_SMEM);

    __nv_bfloat16* acvt = (__nv_bfloat16*)pcng;   // prologue-only bf16 view
    __nv_bfloat16* pglu = (__nv_bfloat16*)pt1;    // glu out (rows of 512 bf16)

    // prologue
    pack_all<<<512, 256>>>(Wcs, Wcb, Wog, Wcs2, Wcb2, Wog2, Wq, Wg, Wk, Wv,
                           W1, W2, Wo, W3, a2q, pwp);
    argmax_tok<<<BN/8, 256>>>(a2t, ptok);
    cvt_hilo<<<(Bb*Tt*Ss/4 + 255)/256, 256>>>(a, acvt, Ss, Bb*Tt*Ss/4);
    gemm_tc<<<dim3(1, (Bb*Tt)/128), 256, GEMM_SMEM>>>(acvt, pwp + (size_t)Ll*2*PL2, paw, 128, Ss);
    addaw_kernel<<<(BN*32)/256, 256>>>(qin, paw, ptok, pq);
    ln_rows<<<BN/8, 256>>>(c, pcn);

    for (int l = 0; l < Ll; l++) {
        __nv_bfloat16* wl = pwp + (size_t)l*2*PL2;
        // all six cn projections: [cs|cb|og|cs2|cb2|og2]
        gemm_tc<<<dim3(6, BN/128), 256, GEMM_SMEM>>>(pcn, wl, pcng, 768, Dd);
        // hcur = ln(q)*sig(cs) + cb  -> bf16 hi|lo
        ew_hcur<<<BN/8, 256>>>(pq, pcng, 768, ph);
        // fused Q|G|K|V projection on unique rows
        gemm_tc<<<dim3(4, BN/128), 256, GEMM_SMEM>>>(ph, wl + 196608, pt2, 512, Dd);
        // attention: gathers K/V via kidx, applies sigmoid(G) gate -> bf16 hi|lo
        attn_kernel<<<dim3(NHh, NWw, Bb), 128>>>(pt2, bias, mask, kidx, pt3);
        // q += sig(og) * (o@Wo)
        gemm_tc<<<dim3(1, BN/128), 256, GEMM_SMEM>>>(pt3, wl + 458752, pt1, 128, Dd);
        ew_resid<<<(BN*32)/256, 256>>>(pq, pcng + 256, 768, pt1);
        // h2 = ln(q)*sig(cs2) + cb2 -> bf16 hi|lo
        ew_hcur<<<BN/8, 256>>>(pq, pcng + 384, 768, ph);
        // FFN
        gemm_tc<<<dim3(4, BN/128), 256, GEMM_SMEM>>>(ph, wl + 327680, pkv, 512, Dd);
        ew_glu<<<(BN*64)/256, 256>>>(pkv, pglu);
        gemm_tc<<<dim3(1, BN/128), 256, GEMM_SMEM>>>(pglu, wl + 491520, pt2, 128, 256);
        ew_resid<<<(BN*32)/256, 256>>>(pq, pcng + 640, 768, pt2);
    }

    // epilogue
    cudaMemsetAsync(psf, 0, (size_t)Bb*Tt*Dd*sizeof(float));
    sfeat_kernel<<<(BN*128)/256, 256>>>(pq, mask, ptok, psf);
    restype_kernel<<<Bb*Tt, 128>>>(psf, Wres, bres, out + (size_t)BN*3);
    rupdate_kernel<<<BN, 128>>>(pq, ln_g, ln_b, Wpos, out);
}